// round 3
// baseline (speedup 1.0000x reference)
#include <cuda_runtime.h>
#include <math.h>

#define Bq 32
#define Tq 256
#define Nq 256
#define Dq 1024
#define Cq 80

// output layout (float32, tuple order)
#define OFF_BOX    (Bq*Tq*Dq)            // 8388608
#define OFF_ACT    (OFF_BOX + Bq*Tq*4)   // 8421376
#define OFF_AGE    (OFF_ACT + Bq*Tq)     // 8429568
#define OFF_HITS   (OFF_AGE + Bq*Tq)     // 8437760
#define OFF_MATCH  (OFF_HITS + Bq*Tq)    // 8445952
#define OFF_SCORES (OFF_MATCH + Bq*Tq)   // 8454144

// scratch (no allocations allowed)
__device__ float g_C[Bq*Tq*Nq];      // cost matrix, 8.4 MB
__device__ float g_tinv[Bq*Tq];
__device__ float g_dinv[Bq*Nq];
__device__ int   g_match[Bq*Tq];
__device__ int   g_stride4;          // active bool storage width flag

// ---------------------------------------------------------------------------
// Probe: is track_active stored 1 byte/elem or 4 bytes/elem?
// Look at byte offsets 1 mod 4 within the first 256 bytes:
//   uint8 bools (p=0.9): those bytes are independent bool values -> ~57/64 nonzero
//   int32 1 / float32 1.0f: byte 1 of each element is always 0x00 -> 0 nonzero
__global__ void detect_kernel(const unsigned char* __restrict__ act) {
    int ones = 0;
    for (int i = 0; i < 64; i++) ones += (act[4 * i + 1] != 0);
    g_stride4 = (ones > 8) ? 0 : 1;
}

__device__ __forceinline__ bool get_active(const void* act, int idx, int s4) {
    if (s4) return ((const int*)act)[idx] != 0;   // int32 or float32: nonzero word == true
    return ((const unsigned char*)act)[idx] != 0;
}

// ---------------------------------------------------------------------------
// Inverse norms for track_memory rows then det_memory rows. One block per row.
__global__ __launch_bounds__(256) void norm_kernel(const float* __restrict__ tm,
                                                   const float* __restrict__ dm) {
    int r = blockIdx.x;
    const float* src;
    float* dst;
    if (r < Bq*Tq) { src = tm + (size_t)r*Dq;            dst = g_tinv + r; }
    else           { src = dm + (size_t)(r - Bq*Tq)*Dq;  dst = g_dinv + (r - Bq*Tq); }
    int t = threadIdx.x;
    float4 v = ((const float4*)src)[t];
    float s = v.x*v.x + v.y*v.y + v.z*v.z + v.w*v.w;
    __shared__ float red[8];
    #pragma unroll
    for (int off = 16; off; off >>= 1) s += __shfl_down_sync(0xffffffffu, s, off);
    if ((t & 31) == 0) red[t >> 5] = s;
    __syncthreads();
    if (t < 8) {
        float x = red[t];
        #pragma unroll
        for (int off = 4; off; off >>= 1) x += __shfl_down_sync(0xffu, x, off);
        if (t == 0) *dst = 1.0f / fmaxf(sqrtf(x), 1e-12f);
    }
}

// ---------------------------------------------------------------------------
// scores[b,n] = max softmax = 1 / sum(exp(l - max)). One warp per row.
__global__ __launch_bounds__(128) void scores_kernel(const float* __restrict__ logits,
                                                     float* __restrict__ out) {
    int row = blockIdx.x * 4 + (threadIdx.x >> 5);
    int lane = threadIdx.x & 31;
    const float* p = logits + (size_t)row * Cq;
    float a = p[lane];
    float b = p[lane + 32];
    bool hasc = (lane + 64) < Cq;
    float c = hasc ? p[lane + 64] : -INFINITY;
    float m = fmaxf(a, fmaxf(b, c));
    #pragma unroll
    for (int off = 16; off; off >>= 1) m = fmaxf(m, __shfl_xor_sync(0xffffffffu, m, off));
    float s = expf(a - m) + expf(b - m) + (hasc ? expf(c - m) : 0.0f);
    #pragma unroll
    for (int off = 16; off; off >>= 1) s += __shfl_xor_sync(0xffffffffu, s, off);
    if (lane == 0) out[row] = 1.0f / s;
}

// ---------------------------------------------------------------------------
// Batched fp32 GEMM (A·B^T) fused with cosine scaling, IoU, active mask.
// Tile: 128 rows (tracks) x 64 cols (dets), BK=16, 256 threads, 8x4 microtile.
__global__ __launch_bounds__(256) void gemm_cmat_kernel(
    const float* __restrict__ tm, const float* __restrict__ dm,
    const float* __restrict__ tb, const float* __restrict__ db,
    const void* __restrict__ act) {
    int b = blockIdx.z;
    int rowBase = blockIdx.y * 128;
    int colBase = blockIdx.x * 64;
    const float* A  = tm + (size_t)b * Tq * Dq;
    const float* Bm = dm + (size_t)b * Nq * Dq;

    __shared__ float As[16][132];
    __shared__ float Bs[16][68];
    __shared__ float4 s_tbox[128];
    __shared__ float4 s_dbox[64];
    __shared__ float s_ti[128], s_di[64];
    __shared__ unsigned char s_a[128];

    int tid = threadIdx.x;
    int tx = tid & 15, ty = tid >> 4;

    float acc[8][4];
    #pragma unroll
    for (int i = 0; i < 8; i++)
        #pragma unroll
        for (int j = 0; j < 4; j++) acc[i][j] = 0.0f;

    for (int k0 = 0; k0 < Dq; k0 += 16) {
        #pragma unroll
        for (int l = 0; l < 2; l++) {
            int idx = tid + l * 256;
            int r = idx >> 2, q = idx & 3;
            float4 v = *(const float4*)(A + (size_t)(rowBase + r) * Dq + k0 + q * 4);
            As[q*4+0][r] = v.x; As[q*4+1][r] = v.y; As[q*4+2][r] = v.z; As[q*4+3][r] = v.w;
        }
        {
            int r = tid >> 2, q = tid & 3;
            float4 v = *(const float4*)(Bm + (size_t)(colBase + r) * Dq + k0 + q * 4);
            Bs[q*4+0][r] = v.x; Bs[q*4+1][r] = v.y; Bs[q*4+2][r] = v.z; Bs[q*4+3][r] = v.w;
        }
        __syncthreads();
        #pragma unroll
        for (int k = 0; k < 16; k++) {
            float4 a0 = *(const float4*)&As[k][ty * 8];
            float4 a1 = *(const float4*)&As[k][ty * 8 + 4];
            float4 bv = *(const float4*)&Bs[k][tx * 4];
            float av[8] = {a0.x, a0.y, a0.z, a0.w, a1.x, a1.y, a1.z, a1.w};
            float bw[4] = {bv.x, bv.y, bv.z, bv.w};
            #pragma unroll
            for (int i = 0; i < 8; i++)
                #pragma unroll
                for (int j = 0; j < 4; j++)
                    acc[i][j] += av[i] * bw[j];
        }
        __syncthreads();
    }

    // epilogue aux loads
    int s4 = g_stride4;
    if (tid < 128) {
        int gt = rowBase + tid;
        s_tbox[tid] = ((const float4*)tb)[b * Tq + gt];
        s_ti[tid]   = g_tinv[b * Tq + gt];
        s_a[tid]    = get_active(act, b * Tq + gt, s4) ? 1 : 0;
    }
    if (tid < 64) {
        int gn = colBase + tid;
        s_dbox[tid] = ((const float4*)db)[b * Nq + gn];
        s_di[tid]   = g_dinv[b * Nq + gn];
    }
    __syncthreads();

    #pragma unroll
    for (int i = 0; i < 8; i++) {
        int lr = ty * 8 + i;
        int gt = rowBase + lr;
        float4 tbx = s_tbox[lr];
        float ti = s_ti[lr];
        bool aa = s_a[lr] != 0;
        float tx1 = tbx.x - 0.5f * tbx.z, tx2 = tbx.x + 0.5f * tbx.z;
        float ty1 = tbx.y - 0.5f * tbx.w, ty2 = tbx.y + 0.5f * tbx.w;
        float tarea = tbx.z * tbx.w;
        float4 o;
        float* op = &o.x;
        #pragma unroll
        for (int j = 0; j < 4; j++) {
            int lc = tx * 4 + j;
            float4 dbx = s_dbox[lc];
            float dx1 = dbx.x - 0.5f * dbx.z, dx2 = dbx.x + 0.5f * dbx.z;
            float dy1 = dbx.y - 0.5f * dbx.w, dy2 = dbx.y + 0.5f * dbx.w;
            float iw = fmaxf(fminf(tx2, dx2) - fmaxf(tx1, dx1), 0.0f);
            float ih = fmaxf(fminf(ty2, dy2) - fmaxf(ty1, dy1), 0.0f);
            float inter = iw * ih;
            float uni = tarea + dbx.z * dbx.w - inter;
            float iou = inter / (uni + 1e-6f);
            float sim = acc[i][j] * ti * s_di[lc];
            float cv = 0.7f * sim + 0.3f * iou;
            op[j] = aa ? cv : -1.0f;
        }
        *(float4*)(g_C + ((size_t)b * Tq + gt) * Nq + colBase + tx * 4) = o;
    }
}

// ---------------------------------------------------------------------------
// Greedy matching. One block per batch; thread t owns track-row t.
// Incremental row maxima: rescan a row only when its argmax column was taken
// and its stored max could still match (>= 0.7). Tie-break = first flat index.
__global__ __launch_bounds__(256) void greedy_kernel() {
    int b = blockIdx.x;
    int t = threadIdx.x;
    const float* row = g_C + ((size_t)b * Tq + t) * Nq;

    __shared__ float s_max[256];
    __shared__ int   s_arg[256];
    __shared__ int   s_col[256];
    __shared__ float s_rv[8];
    __shared__ int   s_ri[8];
    __shared__ float s_bv;
    __shared__ int   s_pd;

    s_col[t] = 0;
    g_match[b * Tq + t] = -1;

    float best = -2.0f; int barg = 0;
    const float4* r4 = (const float4*)row;
    #pragma unroll 8
    for (int q = 0; q < 64; q++) {
        float4 v = r4[q];
        if (v.x > best) { best = v.x; barg = 4*q;   }
        if (v.y > best) { best = v.y; barg = 4*q+1; }
        if (v.z > best) { best = v.z; barg = 4*q+2; }
        if (v.w > best) { best = v.w; barg = 4*q+3; }
    }
    s_max[t] = best; s_arg[t] = barg;
    __syncthreads();

    for (int it = 0; it < 256; it++) {
        float v = s_max[t]; int i = t;
        #pragma unroll
        for (int off = 16; off; off >>= 1) {
            float ov = __shfl_down_sync(0xffffffffu, v, off);
            int   oi = __shfl_down_sync(0xffffffffu, i, off);
            if (ov > v || (ov == v && oi < i)) { v = ov; i = oi; }
        }
        if ((t & 31) == 0) { s_rv[t >> 5] = v; s_ri[t >> 5] = i; }
        __syncthreads();
        if (t == 0) {
            float bv = s_rv[0]; int bi = s_ri[0];
            #pragma unroll
            for (int w = 1; w < 8; w++)
                if (s_rv[w] > bv || (s_rv[w] == bv && s_ri[w] < bi)) { bv = s_rv[w]; bi = s_ri[w]; }
            s_bv = bv;
            if (bv >= 0.7f) {
                int d = s_arg[bi];
                g_match[b * Tq + bi] = d;
                s_col[d] = 1;
                s_max[bi] = -3.0f;
                s_pd = d;
            }
        }
        __syncthreads();
        if (s_bv < 0.7f) break;   // remaining iterations are no-ops in the reference
        int pd = s_pd;
        float mv = s_max[t];
        if (mv >= 0.7f && s_arg[t] == pd) {
            float nb = -2.0f; int na = 0;
            #pragma unroll 4
            for (int n = 0; n < 256; n++) {
                float c = row[n];
                if (!s_col[n] && c > nb) { nb = c; na = n; }
            }
            s_max[t] = nb; s_arg[t] = na;
        }
        __syncthreads();
    }
}

// ---------------------------------------------------------------------------
// Output assembly. Blocks [0, B*T): new_mem row copy/gather.
// Blocks [B*T, B*T+B): per-batch scalar state + boxes.
__global__ __launch_bounds__(256) void output_kernel(
    const float* __restrict__ tm, const float* __restrict__ dm,
    const float* __restrict__ tb, const float* __restrict__ db,
    const void* __restrict__ act, const int* __restrict__ age,
    const int* __restrict__ hits, float* __restrict__ out) {
    int blk = blockIdx.x;
    if (blk < Bq * Tq) {
        int b = blk >> 8;
        int m = g_match[blk];
        const float* src = (m >= 0) ? (dm + ((size_t)b * Nq + m) * Dq)
                                    : (tm + (size_t)blk * Dq);
        float4 v = ((const float4*)src)[threadIdx.x];
        ((float4*)(out + (size_t)blk * Dq))[threadIdx.x] = v;
    } else {
        int b = blk - Bq * Tq;
        int t = threadIdx.x;
        int idx = b * Tq + t;
        int m = g_match[idx];
        bool matched = m >= 0;
        int d = matched ? m : 0;
        int s4 = g_stride4;
        bool a = get_active(act, idx, s4);
        int h = hits[idx] + (matched ? 1 : 0);
        bool unm = a && !matched;
        int ag = age[idx];
        int newage = matched ? 0 : (unm ? ag + 1 : ag);
        bool newact = matched ? true : (unm ? (newage <= 10) : a);
        float4 bx = matched ? ((const float4*)db)[b * Nq + d]
                            : ((const float4*)tb)[idx];
        ((float4*)(out + OFF_BOX))[idx] = bx;
        out[OFF_ACT   + idx] = newact ? 1.0f : 0.0f;
        out[OFF_AGE   + idx] = (float)newage;
        out[OFF_HITS  + idx] = (float)h;
        out[OFF_MATCH + idx] = (float)m;
    }
}

// ---------------------------------------------------------------------------
extern "C" void kernel_launch(void* const* d_in, const int* in_sizes, int n_in,
                              void* d_out, int out_size) {
    const float* tm   = (const float*)d_in[0];   // track_memory  [B,T,D]
    const float* tb   = (const float*)d_in[1];   // track_boxes   [B,T,4]
    const void*  act  = d_in[2];                 // track_active  [B,T] (bool, width probed)
    const int*   age  = (const int*)d_in[3];     // track_age     [B,T]
    const int*   hits = (const int*)d_in[4];     // track_hits    [B,T]
    const float* db   = (const float*)d_in[5];   // det_boxes     [B,N,4]
    const float* dm   = (const float*)d_in[6];   // det_memory    [B,N,D]
    const float* cl   = (const float*)d_in[7];   // class_logits  [B,N,C]
    float* out = (float*)d_out;

    detect_kernel<<<1, 1>>>((const unsigned char*)act);
    norm_kernel<<<Bq*(Tq + Nq), 256>>>(tm, dm);
    scores_kernel<<<(Bq*Nq)/4, 128>>>(cl, out + OFF_SCORES);
    dim3 g(Nq/64, Tq/128, Bq);
    gemm_cmat_kernel<<<g, 256>>>(tm, dm, tb, db, act);
    greedy_kernel<<<Bq, 256>>>();
    output_kernel<<<Bq*Tq + Bq, 256>>>(tm, dm, tb, db, act, age, hits, out);
}

// round 4
// speedup vs baseline: 1.2825x; 1.2825x over previous
#include <cuda_runtime.h>
#include <math.h>

#define Bq 32
#define Tq 256
#define Nq 256
#define Dq 1024
#define Cq 80

// output layout (float32, tuple order)
#define OFF_BOX    (Bq*Tq*Dq)
#define OFF_ACT    (OFF_BOX + Bq*Tq*4)
#define OFF_AGE    (OFF_ACT + Bq*Tq)
#define OFF_HITS   (OFF_AGE + Bq*Tq)
#define OFF_MATCH  (OFF_HITS + Bq*Tq)
#define OFF_SCORES (OFF_MATCH + Bq*Tq)

typedef unsigned long long ull;

// scratch
__device__ float g_C[Bq*Tq*Nq];      // cost matrix, 8.4 MB
__device__ int   g_match[Bq*Tq];
__device__ int   g_stride4;

// ---------------------------------------------------------------------------
__device__ __forceinline__ bool get_active(const void* act, int idx, int s4) {
    if (s4) return ((const int*)act)[idx] != 0;
    return ((const unsigned char*)act)[idx] != 0;
}

__device__ __forceinline__ ull pack2(float x, float y) {
    ull r; asm("mov.b64 %0, {%1, %2};" : "=l"(r) : "f"(x), "f"(y)); return r;
}
__device__ __forceinline__ void unpack2(ull v, float& x, float& y) {
    asm("mov.b64 {%0, %1}, %2;" : "=f"(x), "=f"(y) : "l"(v));
}
__device__ __forceinline__ void ffma2(ull& d, ull a, ull b) {
    asm("fma.rn.f32x2 %0, %1, %2, %3;" : "=l"(d) : "l"(a), "l"(b), "l"(d));
}

// ---------------------------------------------------------------------------
// scores[b,n] = 1 / sum(exp(l - max)). One warp per row. Block 0 thread 0 also
// probes track_active storage width (byte offsets 1 mod 4: uint8 bools ~90%
// nonzero; int32/float32 byte1 always 0).
__global__ __launch_bounds__(128) void scores_kernel(const float* __restrict__ logits,
                                                     const unsigned char* __restrict__ act,
                                                     float* __restrict__ out) {
    if (blockIdx.x == 0 && threadIdx.x == 0) {
        int ones = 0;
        for (int i = 0; i < 64; i++) ones += (act[4 * i + 1] != 0);
        g_stride4 = (ones > 8) ? 0 : 1;
    }
    int row = blockIdx.x * 4 + (threadIdx.x >> 5);
    int lane = threadIdx.x & 31;
    const float* p = logits + (size_t)row * Cq;
    float a = p[lane];
    float b = p[lane + 32];
    bool hasc = (lane + 64) < Cq;
    float c = hasc ? p[lane + 64] : -INFINITY;
    float m = fmaxf(a, fmaxf(b, c));
    #pragma unroll
    for (int off = 16; off; off >>= 1) m = fmaxf(m, __shfl_xor_sync(0xffffffffu, m, off));
    float s = expf(a - m) + expf(b - m) + (hasc ? expf(c - m) : 0.0f);
    #pragma unroll
    for (int off = 16; off; off >>= 1) s += __shfl_xor_sync(0xffffffffu, s, off);
    if (lane == 0) out[row] = 1.0f / s;
}

// ---------------------------------------------------------------------------
// FFMA2 GEMM (A·B^T) fused with row-norm computation, cosine scaling, IoU,
// active mask. 128x128 tile, BK=16, 256 threads, 8x8 split microtile.
__global__ __launch_bounds__(256) void gemm_cmat_kernel(
    const float* __restrict__ tm, const float* __restrict__ dm,
    const float* __restrict__ tb, const float* __restrict__ db,
    const void* __restrict__ act) {
    int b = blockIdx.z;
    int rowBase = blockIdx.y * 128;
    int colBase = blockIdx.x * 128;
    const float* A  = tm + (size_t)b * Tq * Dq;
    const float* Bm = dm + (size_t)b * Nq * Dq;

    __shared__ float As[16][132];
    __shared__ float Bs[16][132];
    __shared__ float s_an[128], s_bn[128];
    __shared__ float4 s_tbox[128];
    __shared__ float4 s_dbox[128];
    __shared__ unsigned char s_a[128];

    int tid = threadIdx.x;
    int tx = tid & 15, ty = tid >> 4;
    int ar = tid >> 2;        // 0..63
    int aq = tid & 3;         // quarter of the 16-k chunk

    const float* Aptr0 = A  + (size_t)(rowBase + ar)      * Dq + aq * 4;
    const float* Aptr1 = A  + (size_t)(rowBase + ar + 64) * Dq + aq * 4;
    const float* Bptr0 = Bm + (size_t)(colBase + ar)      * Dq + aq * 4;
    const float* Bptr1 = Bm + (size_t)(colBase + ar + 64) * Dq + aq * 4;

    ull acc[8][4];
    #pragma unroll
    for (int i = 0; i < 8; i++)
        #pragma unroll
        for (int j = 0; j < 4; j++) acc[i][j] = 0ull;

    float asum0 = 0.f, asum1 = 0.f, bsum0 = 0.f, bsum1 = 0.f;

    float4 ga0 = *(const float4*)(Aptr0);
    float4 ga1 = *(const float4*)(Aptr1);
    float4 gb0 = *(const float4*)(Bptr0);
    float4 gb1 = *(const float4*)(Bptr1);

    for (int k0 = 0; k0 < Dq; k0 += 16) {
        As[aq*4+0][ar] = ga0.x; As[aq*4+1][ar] = ga0.y; As[aq*4+2][ar] = ga0.z; As[aq*4+3][ar] = ga0.w;
        As[aq*4+0][ar+64] = ga1.x; As[aq*4+1][ar+64] = ga1.y; As[aq*4+2][ar+64] = ga1.z; As[aq*4+3][ar+64] = ga1.w;
        Bs[aq*4+0][ar] = gb0.x; Bs[aq*4+1][ar] = gb0.y; Bs[aq*4+2][ar] = gb0.z; Bs[aq*4+3][ar] = gb0.w;
        Bs[aq*4+0][ar+64] = gb1.x; Bs[aq*4+1][ar+64] = gb1.y; Bs[aq*4+2][ar+64] = gb1.z; Bs[aq*4+3][ar+64] = gb1.w;
        asum0 += ga0.x*ga0.x + ga0.y*ga0.y + ga0.z*ga0.z + ga0.w*ga0.w;
        asum1 += ga1.x*ga1.x + ga1.y*ga1.y + ga1.z*ga1.z + ga1.w*ga1.w;
        bsum0 += gb0.x*gb0.x + gb0.y*gb0.y + gb0.z*gb0.z + gb0.w*gb0.w;
        bsum1 += gb1.x*gb1.x + gb1.y*gb1.y + gb1.z*gb1.z + gb1.w*gb1.w;
        __syncthreads();
        if (k0 < Dq - 16) {
            ga0 = *(const float4*)(Aptr0 + k0 + 16);
            ga1 = *(const float4*)(Aptr1 + k0 + 16);
            gb0 = *(const float4*)(Bptr0 + k0 + 16);
            gb1 = *(const float4*)(Bptr1 + k0 + 16);
        }
        #pragma unroll
        for (int k = 0; k < 16; k++) {
            float4 a0 = *(const float4*)&As[k][ty * 4];
            float4 a1 = *(const float4*)&As[k][64 + ty * 4];
            float4 b0 = *(const float4*)&Bs[k][tx * 4];
            float4 b1 = *(const float4*)&Bs[k][64 + tx * 4];
            ull bb[4];
            bb[0] = pack2(b0.x, b0.y); bb[1] = pack2(b0.z, b0.w);
            bb[2] = pack2(b1.x, b1.y); bb[3] = pack2(b1.z, b1.w);
            float av[8] = {a0.x, a0.y, a0.z, a0.w, a1.x, a1.y, a1.z, a1.w};
            #pragma unroll
            for (int i = 0; i < 8; i++) {
                ull aa = pack2(av[i], av[i]);
                #pragma unroll
                for (int j = 0; j < 4; j++) ffma2(acc[i][j], aa, bb[j]);
            }
        }
        __syncthreads();
    }

    // reduce sumsq over the 4 lanes sharing a row (lanes grouped by tid>>2)
    asum0 += __shfl_down_sync(0xffffffffu, asum0, 2); asum0 += __shfl_down_sync(0xffffffffu, asum0, 1);
    asum1 += __shfl_down_sync(0xffffffffu, asum1, 2); asum1 += __shfl_down_sync(0xffffffffu, asum1, 1);
    bsum0 += __shfl_down_sync(0xffffffffu, bsum0, 2); bsum0 += __shfl_down_sync(0xffffffffu, bsum0, 1);
    bsum1 += __shfl_down_sync(0xffffffffu, bsum1, 2); bsum1 += __shfl_down_sync(0xffffffffu, bsum1, 1);
    if (aq == 0) {
        s_an[ar] = asum0; s_an[ar + 64] = asum1;
        s_bn[ar] = bsum0; s_bn[ar + 64] = bsum1;
    }
    int s4 = g_stride4;
    if (tid < 128) {
        s_tbox[tid] = ((const float4*)tb)[b * Tq + rowBase + tid];
        s_dbox[tid] = ((const float4*)db)[b * Nq + colBase + tid];
        s_a[tid]    = get_active(act, b * Tq + rowBase + tid, s4) ? 1 : 0;
    }
    __syncthreads();

    // per-thread column data
    int cols[8]; float di[8]; float4 dbx[8];
    #pragma unroll
    for (int j = 0; j < 8; j++) {
        int lc = (j < 4) ? (tx * 4 + j) : (64 + tx * 4 + j - 4);
        cols[j] = lc;
        di[j] = 1.0f / fmaxf(sqrtf(s_bn[lc]), 1e-12f);
        dbx[j] = s_dbox[lc];
    }

    #pragma unroll
    for (int i = 0; i < 8; i++) {
        int lr = (i < 4) ? (ty * 4 + i) : (64 + ty * 4 + i - 4);
        int gt = rowBase + lr;
        float ti = 1.0f / fmaxf(sqrtf(s_an[lr]), 1e-12f);
        float4 tbx = s_tbox[lr];
        bool aa = s_a[lr] != 0;
        float tx1 = tbx.x - 0.5f * tbx.z, tx2 = tbx.x + 0.5f * tbx.z;
        float ty1 = tbx.y - 0.5f * tbx.w, ty2 = tbx.y + 0.5f * tbx.w;
        float tarea = tbx.z * tbx.w;
        float c8[8];
        #pragma unroll
        for (int j = 0; j < 4; j++) unpack2(acc[i][j], c8[2*j], c8[2*j+1]);
        float o[8];
        #pragma unroll
        for (int j = 0; j < 8; j++) {
            float4 dv = dbx[j];
            float dx1 = dv.x - 0.5f * dv.z, dx2 = dv.x + 0.5f * dv.z;
            float dy1 = dv.y - 0.5f * dv.w, dy2 = dv.y + 0.5f * dv.w;
            float iw = fmaxf(fminf(tx2, dx2) - fmaxf(tx1, dx1), 0.0f);
            float ih = fmaxf(fminf(ty2, dy2) - fmaxf(ty1, dy1), 0.0f);
            float inter = iw * ih;
            float uni = tarea + dv.z * dv.w - inter;
            float iou = inter / (uni + 1e-6f);
            float sim = c8[j] * ti * di[j];
            float cv = 0.7f * sim + 0.3f * iou;
            o[j] = aa ? cv : -1.0f;
        }
        float* dst = g_C + ((size_t)b * Tq + gt) * Nq + colBase;
        *(float4*)(dst + tx * 4)      = make_float4(o[0], o[1], o[2], o[3]);
        *(float4*)(dst + 64 + tx * 4) = make_float4(o[4], o[5], o[6], o[7]);
    }
}

// ---------------------------------------------------------------------------
// Greedy matching, one warp per batch. Fast path: all candidates (row max
// >= 0.7) have distinct argmax columns -> greedy order irrelevant -> accept
// all at once. Warp-synchronous sequential fallback otherwise.
__global__ __launch_bounds__(32) void greedy_kernel() {
    int b = blockIdx.x;
    int l = threadIdx.x;

    float rmax[8]; int rarg[8];
    #pragma unroll
    for (int i = 0; i < 8; i++) {
        int row = i * 32 + l;
        const float4* r4 = (const float4*)(g_C + ((size_t)b * Tq + row) * Nq);
        float best = -2.0f; int arg = 0;
        #pragma unroll 8
        for (int q = 0; q < 64; q++) {
            float4 v = r4[q];
            if (v.x > best) { best = v.x; arg = 4*q;   }
            if (v.y > best) { best = v.y; arg = 4*q+1; }
            if (v.z > best) { best = v.z; arg = 4*q+2; }
            if (v.w > best) { best = v.w; arg = 4*q+3; }
        }
        rmax[i] = best; rarg[i] = arg;
    }

    // fast-path distinctness check
    unsigned cm[8] = {0,0,0,0,0,0,0,0};
    int cnt = 0;
    #pragma unroll
    for (int i = 0; i < 8; i++)
        if (rmax[i] >= 0.7f) { cnt++; cm[rarg[i] >> 5] |= 1u << (rarg[i] & 31); }
    int lpop = 0;
    #pragma unroll
    for (int w = 0; w < 8; w++) lpop += __popc(cm[w]);
    int totc = __reduce_add_sync(0xffffffffu, cnt);
    int orp = 0;
    #pragma unroll
    for (int w = 0; w < 8; w++) orp += __popc(__reduce_or_sync(0xffffffffu, cm[w]));
    bool dup = (lpop != cnt);
    bool conflict = __any_sync(0xffffffffu, dup) || (orp != totc);

    if (!conflict) {
        #pragma unroll
        for (int i = 0; i < 8; i++)
            g_match[b * Tq + i * 32 + l] = (rmax[i] >= 0.7f) ? rarg[i] : -1;
        return;
    }

    // slow path: exact sequential greedy (value desc, flat-index asc tiebreak)
    #pragma unroll
    for (int i = 0; i < 8; i++) g_match[b * Tq + i * 32 + l] = -1;
    unsigned taken[8] = {0,0,0,0,0,0,0,0};
    for (int it = 0; it < 256; it++) {
        float bv = rmax[0]; int bi = 0;
        #pragma unroll
        for (int i = 1; i < 8; i++) if (rmax[i] > bv) { bv = rmax[i]; bi = i; }
        int brow = bi * 32 + l;
        #pragma unroll
        for (int off = 16; off; off >>= 1) {
            float ov = __shfl_xor_sync(0xffffffffu, bv, off);
            int orow  = __shfl_xor_sync(0xffffffffu, brow, off);
            if (ov > bv || (ov == bv && orow < brow)) { bv = ov; brow = orow; }
        }
        if (bv < 0.7f) break;
        int ol = brow & 31, oi = brow >> 5;
        int d = __shfl_sync(0xffffffffu, rarg[oi], ol);
        taken[d >> 5] |= 1u << (d & 31);
        if (l == ol) { g_match[b * Tq + brow] = d; rmax[oi] = -3.0f; }
        #pragma unroll
        for (int i = 0; i < 8; i++) {
            if (rmax[i] >= 0.7f && rarg[i] == d) {
                int row = i * 32 + l;
                const float* rr = g_C + ((size_t)b * Tq + row) * Nq;
                float best = -2.0f; int arg = 0;
                for (int n = 0; n < 256; n++) {
                    if (taken[n >> 5] & (1u << (n & 31))) continue;
                    float c = rr[n];
                    if (c > best) { best = c; arg = n; }
                }
                rmax[i] = best; rarg[i] = arg;
            }
        }
    }
}

// ---------------------------------------------------------------------------
// Output assembly.
__global__ __launch_bounds__(256) void output_kernel(
    const float* __restrict__ tm, const float* __restrict__ dm,
    const float* __restrict__ tb, const float* __restrict__ db,
    const void* __restrict__ act, const int* __restrict__ age,
    const int* __restrict__ hits, float* __restrict__ out) {
    int blk = blockIdx.x;
    if (blk < Bq * Tq) {
        int b = blk >> 8;
        int m = g_match[blk];
        const float* src = (m >= 0) ? (dm + ((size_t)b * Nq + m) * Dq)
                                    : (tm + (size_t)blk * Dq);
        float4 v = ((const float4*)src)[threadIdx.x];
        ((float4*)(out + (size_t)blk * Dq))[threadIdx.x] = v;
    } else {
        int b = blk - Bq * Tq;
        int t = threadIdx.x;
        int idx = b * Tq + t;
        int m = g_match[idx];
        bool matched = m >= 0;
        int d = matched ? m : 0;
        int s4 = g_stride4;
        bool a = get_active(act, idx, s4);
        int h = hits[idx] + (matched ? 1 : 0);
        bool unm = a && !matched;
        int ag = age[idx];
        int newage = matched ? 0 : (unm ? ag + 1 : ag);
        bool newact = matched ? true : (unm ? (newage <= 10) : a);
        float4 bx = matched ? ((const float4*)db)[b * Nq + d]
                            : ((const float4*)tb)[idx];
        ((float4*)(out + OFF_BOX))[idx] = bx;
        out[OFF_ACT   + idx] = newact ? 1.0f : 0.0f;
        out[OFF_AGE   + idx] = (float)newage;
        out[OFF_HITS  + idx] = (float)h;
        out[OFF_MATCH + idx] = (float)m;
    }
}

// ---------------------------------------------------------------------------
extern "C" void kernel_launch(void* const* d_in, const int* in_sizes, int n_in,
                              void* d_out, int out_size) {
    const float* tm   = (const float*)d_in[0];
    const float* tb   = (const float*)d_in[1];
    const void*  act  = d_in[2];
    const int*   age  = (const int*)d_in[3];
    const int*   hits = (const int*)d_in[4];
    const float* db   = (const float*)d_in[5];
    const float* dm   = (const float*)d_in[6];
    const float* cl   = (const float*)d_in[7];
    float* out = (float*)d_out;

    scores_kernel<<<(Bq*Nq)/4, 128>>>(cl, (const unsigned char*)act, out + OFF_SCORES);
    dim3 g(Nq/128, Tq/128, Bq);
    gemm_cmat_kernel<<<g, 256>>>(tm, dm, tb, db, act);
    greedy_kernel<<<Bq, 32>>>();
    output_kernel<<<Bq*Tq + Bq, 256>>>(tm, dm, tb, db, act, age, hits, out);
}

// round 8
// speedup vs baseline: 2.4684x; 1.9246x over previous
#include <cuda_runtime.h>
#include <math.h>
#include <stdint.h>

#define Bq 32
#define Tq 256
#define Nq 256
#define Dq 1024
#define Cq 80

// output layout (float32, tuple order)
#define OFF_BOX    (Bq*Tq*Dq)
#define OFF_ACT    (OFF_BOX + Bq*Tq*4)
#define OFF_AGE    (OFF_ACT + Bq*Tq)
#define OFF_HITS   (OFF_AGE + Bq*Tq)
#define OFF_MATCH  (OFF_HITS + Bq*Tq)
#define OFF_SCORES (OFF_MATCH + Bq*Tq)

// scratch
__device__ float  g_C[Bq*Tq*Nq];      // cost matrix (fallback path)
__device__ float2 g_rmax[Bq*Tq*2];    // per-(row, colTile) max/arg
__device__ int    g_match[Bq*Tq];
__device__ int    g_stride4;

// ---------------------------------------------------------------------------
__device__ __forceinline__ bool get_active(const void* act, int idx, int s4) {
    if (s4) return ((const int*)act)[idx] != 0;
    return ((const unsigned char*)act)[idx] != 0;
}

// bf16x2 mma: D(f32x4) += A(bf16 m16k16) * B(bf16 k16n8)
__device__ __forceinline__ void mma16816(float* d, const uint32_t* a, const uint32_t* b) {
    asm volatile(
        "mma.sync.aligned.m16n8k16.row.col.f32.bf16.bf16.f32 "
        "{%0,%1,%2,%3}, {%4,%5,%6,%7}, {%8,%9}, {%0,%1,%2,%3};"
        : "+f"(d[0]), "+f"(d[1]), "+f"(d[2]), "+f"(d[3])
        : "r"(a[0]), "r"(a[1]), "r"(a[2]), "r"(a[3]), "r"(b[0]), "r"(b[1]));
}

// fp32 float4 -> (hi bf16x2 pair, lo bf16x2 pair)
__device__ __forceinline__ void split4(float4 v, uint32_t& h0, uint32_t& h1,
                                       uint32_t& l0, uint32_t& l1) {
    asm("cvt.rn.bf16x2.f32 %0, %1, %2;" : "=r"(h0) : "f"(v.y), "f"(v.x));
    asm("cvt.rn.bf16x2.f32 %0, %1, %2;" : "=r"(h1) : "f"(v.w), "f"(v.z));
    float rx = v.x - __uint_as_float(h0 << 16);
    float ry = v.y - __uint_as_float(h0 & 0xFFFF0000u);
    float rz = v.z - __uint_as_float(h1 << 16);
    float rw = v.w - __uint_as_float(h1 & 0xFFFF0000u);
    asm("cvt.rn.bf16x2.f32 %0, %1, %2;" : "=r"(l0) : "f"(ry), "f"(rx));
    asm("cvt.rn.bf16x2.f32 %0, %1, %2;" : "=r"(l1) : "f"(rw), "f"(rz));
}

// ---------------------------------------------------------------------------
// scores + active-width probe
__global__ __launch_bounds__(128) void scores_kernel(const float* __restrict__ logits,
                                                     const unsigned char* __restrict__ act,
                                                     float* __restrict__ out) {
    if (blockIdx.x == 0 && threadIdx.x == 0) {
        int ones = 0;
        for (int i = 0; i < 64; i++) ones += (act[4 * i + 1] != 0);
        g_stride4 = (ones > 8) ? 0 : 1;
    }
    int row = blockIdx.x * 4 + (threadIdx.x >> 5);
    int lane = threadIdx.x & 31;
    const float* p = logits + (size_t)row * Cq;
    float a = p[lane];
    float b = p[lane + 32];
    bool hasc = (lane + 64) < Cq;
    float c = hasc ? p[lane + 64] : -INFINITY;
    float m = fmaxf(a, fmaxf(b, c));
    #pragma unroll
    for (int off = 16; off; off >>= 1) m = fmaxf(m, __shfl_xor_sync(0xffffffffu, m, off));
    float s = expf(a - m) + expf(b - m) + (hasc ? expf(c - m) : 0.0f);
    #pragma unroll
    for (int off = 16; off; off >>= 1) s += __shfl_xor_sync(0xffffffffu, s, off);
    if (lane == 0) out[row] = 1.0f / s;
}

// ---------------------------------------------------------------------------
// HMMA (mma.sync bf16) 3-pass split GEMM + fused norms + IoU/cost epilogue
// + per-row maxima. 128x128 tile per CTA, K chunks of 32, 8 warps 4x2.
#define KST 20   // smem row stride in uint32 (conflict-free: 20*q mod 32 distinct)

__global__ __launch_bounds__(256) void gemm_cmat_mma(
    const float* __restrict__ tm, const float* __restrict__ dm,
    const float* __restrict__ tb, const float* __restrict__ db,
    const void* __restrict__ act) {
    __shared__ uint32_t As_hi[128*KST], As_lo[128*KST];
    __shared__ uint32_t Bs_hi[128*KST], Bs_lo[128*KST];
    __shared__ float s_an[128], s_bn[128], s_dinv[128];
    __shared__ float4 s_tbox[128], s_dbox[128];
    __shared__ float2 s_rmv[2][128];

    int tid = threadIdx.x;
    int b = blockIdx.z, rowBase = blockIdx.y * 128, colBase = blockIdx.x * 128;

    int r = tid >> 1, h = tid & 1;           // load role: row 0..127, k-half
    const float* aP = tm + ((size_t)(b * Tq + rowBase + r)) * Dq + h * 16;
    const float* bP = dm + ((size_t)(b * Nq + colBase + r)) * Dq + h * 16;

    int lane = tid & 31, wid = tid >> 5;
    int wm = wid & 3, wn = wid >> 2;         // warp tile: rows wm*32+, cols wn*64+
    int qrow = lane >> 2, qk = lane & 3;

    float acc[2][8][4];
    #pragma unroll
    for (int mi = 0; mi < 2; mi++)
        #pragma unroll
        for (int ni = 0; ni < 8; ni++)
            #pragma unroll
            for (int q = 0; q < 4; q++) acc[mi][ni][q] = 0.0f;

    float asum = 0.f, bsum = 0.f;

    float4 ra[4], rb[4];
    #pragma unroll
    for (int q = 0; q < 4; q++) {
        ra[q] = *(const float4*)(aP + q * 4);
        rb[q] = *(const float4*)(bP + q * 4);
    }

    for (int c = 0; c < 32; c++) {
        if (c) __syncthreads();              // previous compute done before overwrite
        #pragma unroll
        for (int q = 0; q < 4; q++) {
            float4 v = ra[q];
            asum += v.x*v.x + v.y*v.y + v.z*v.z + v.w*v.w;
            uint32_t h0,h1,l0,l1; split4(v, h0,h1,l0,l1);
            int kp = r * KST + h * 8 + q * 2;
            As_hi[kp] = h0; As_hi[kp+1] = h1;
            As_lo[kp] = l0; As_lo[kp+1] = l1;
            v = rb[q];
            bsum += v.x*v.x + v.y*v.y + v.z*v.z + v.w*v.w;
            split4(v, h0,h1,l0,l1);
            Bs_hi[kp] = h0; Bs_hi[kp+1] = h1;
            Bs_lo[kp] = l0; Bs_lo[kp+1] = l1;
        }
        __syncthreads();
        if (c < 31) {
            int k0 = (c + 1) * 32;
            #pragma unroll
            for (int q = 0; q < 4; q++) {
                ra[q] = *(const float4*)(aP + k0 + q * 4);
                rb[q] = *(const float4*)(bP + k0 + q * 4);
            }
        }
        #pragma unroll
        for (int s = 0; s < 2; s++) {
            int kb = s * 8 + qk;
            uint32_t ah[2][4], al[2][4], bh[8][2], bl[8][2];
            #pragma unroll
            for (int mi = 0; mi < 2; mi++) {
                int row = wm * 32 + mi * 16 + qrow;
                ah[mi][0] = As_hi[row*KST + kb];       ah[mi][1] = As_hi[(row+8)*KST + kb];
                ah[mi][2] = As_hi[row*KST + kb + 4];   ah[mi][3] = As_hi[(row+8)*KST + kb + 4];
                al[mi][0] = As_lo[row*KST + kb];       al[mi][1] = As_lo[(row+8)*KST + kb];
                al[mi][2] = As_lo[row*KST + kb + 4];   al[mi][3] = As_lo[(row+8)*KST + kb + 4];
            }
            #pragma unroll
            for (int ni = 0; ni < 8; ni++) {
                int col = wn * 64 + ni * 8 + qrow;
                bh[ni][0] = Bs_hi[col*KST + kb];  bh[ni][1] = Bs_hi[col*KST + kb + 4];
                bl[ni][0] = Bs_lo[col*KST + kb];  bl[ni][1] = Bs_lo[col*KST + kb + 4];
            }
            #pragma unroll
            for (int mi = 0; mi < 2; mi++)
                #pragma unroll
                for (int ni = 0; ni < 8; ni++) {
                    mma16816(acc[mi][ni], ah[mi], bh[ni]);
                    mma16816(acc[mi][ni], ah[mi], bl[ni]);
                    mma16816(acc[mi][ni], al[mi], bh[ni]);
                }
        }
    }

    // norms: partner thread (tid^1) holds the other k-half of the same row
    asum += __shfl_xor_sync(0xffffffffu, asum, 1);
    bsum += __shfl_xor_sync(0xffffffffu, bsum, 1);
    __syncthreads();
    if ((tid & 1) == 0) { s_an[r] = asum; s_bn[r] = bsum; }
    if (tid < 128) {
        s_tbox[tid] = ((const float4*)tb)[b * Tq + rowBase + tid];
        s_dbox[tid] = ((const float4*)db)[b * Nq + colBase + tid];
    }
    __syncthreads();
    if (tid < 128) s_dinv[tid] = 1.0f / fmaxf(sqrtf(s_bn[tid]), 1e-12f);
    __syncthreads();

    int s4 = g_stride4;
    #pragma unroll
    for (int mi = 0; mi < 2; mi++) {
        #pragma unroll
        for (int half = 0; half < 2; half++) {
            int lr = wm * 32 + mi * 16 + half * 8 + qrow;
            int gt = rowBase + lr;
            float ti = 1.0f / fmaxf(sqrtf(s_an[lr]), 1e-12f);
            float4 tbx = s_tbox[lr];
            bool aa = get_active(act, b * Tq + gt, s4);
            float tx1 = tbx.x - 0.5f * tbx.z, tx2 = tbx.x + 0.5f * tbx.z;
            float ty1 = tbx.y - 0.5f * tbx.w, ty2 = tbx.y + 0.5f * tbx.w;
            float tarea = tbx.z * tbx.w;
            float best = -2.0f; int barg = 0;
            float* dst = g_C + ((size_t)(b * Tq + gt)) * Nq + colBase;
            #pragma unroll
            for (int ni = 0; ni < 8; ni++) {
                int lc = wn * 64 + ni * 8 + qk * 2;
                float2 o;
                #pragma unroll
                for (int j = 0; j < 2; j++) {
                    float dot = acc[mi][ni][half * 2 + j];
                    float4 dv = s_dbox[lc + j];
                    float dx1 = dv.x - 0.5f * dv.z, dx2 = dv.x + 0.5f * dv.z;
                    float dy1 = dv.y - 0.5f * dv.w, dy2 = dv.y + 0.5f * dv.w;
                    float iw = fmaxf(fminf(tx2, dx2) - fmaxf(tx1, dx1), 0.0f);
                    float ih = fmaxf(fminf(ty2, dy2) - fmaxf(ty1, dy1), 0.0f);
                    float inter = iw * ih;
                    float uni = tarea + dv.z * dv.w - inter;
                    float iou = inter / (uni + 1e-6f);
                    float cv = 0.7f * (dot * ti * s_dinv[lc + j]) + 0.3f * iou;
                    cv = aa ? cv : -1.0f;
                    if (cv > best) { best = cv; barg = lc + j; }
                    (&o.x)[j] = cv;
                }
                *(float2*)(dst + lc) = o;
            }
            // row-max reduce over the 4 lanes sharing this row (vary qk)
            #pragma unroll
            for (int off = 1; off <= 2; off <<= 1) {
                float ov = __shfl_xor_sync(0xffffffffu, best, off);
                int   oa = __shfl_xor_sync(0xffffffffu, barg, off);
                if (ov > best || (ov == best && oa < barg)) { best = ov; barg = oa; }
            }
            if (qk == 0) s_rmv[wn][lr] = make_float2(best, __int_as_float(colBase + barg));
        }
    }
    __syncthreads();
    if (tid < 128) {
        float2 m0 = s_rmv[0][tid], m1 = s_rmv[1][tid];
        float2 mm = (m1.x > m0.x) ? m1 : m0;
        g_rmax[(b * Tq + rowBase + tid) * 2 + blockIdx.x] = mm;
    }
}

// ---------------------------------------------------------------------------
// Greedy matching, one warp per batch. Fast path reads g_rmax only.
__global__ __launch_bounds__(32) void greedy_kernel() {
    int b = blockIdx.x;
    int l = threadIdx.x;

    float rmax[8]; int rarg[8];
    #pragma unroll
    for (int i = 0; i < 8; i++) {
        int row = i * 32 + l;
        float2 m0 = g_rmax[(b * Tq + row) * 2 + 0];
        float2 m1 = g_rmax[(b * Tq + row) * 2 + 1];
        float v = m0.x; int a = __float_as_int(m0.y);
        if (m1.x > v) { v = m1.x; a = __float_as_int(m1.y); }
        rmax[i] = v; rarg[i] = a;
    }

    // fast-path distinctness check
    unsigned cm[8] = {0,0,0,0,0,0,0,0};
    int cnt = 0;
    #pragma unroll
    for (int i = 0; i < 8; i++)
        if (rmax[i] >= 0.7f) { cnt++; cm[rarg[i] >> 5] |= 1u << (rarg[i] & 31); }
    int lpop = 0;
    #pragma unroll
    for (int w = 0; w < 8; w++) lpop += __popc(cm[w]);
    int totc = __reduce_add_sync(0xffffffffu, cnt);
    int orp = 0;
    #pragma unroll
    for (int w = 0; w < 8; w++) orp += __popc(__reduce_or_sync(0xffffffffu, cm[w]));
    bool dup = (lpop != cnt);
    bool conflict = __any_sync(0xffffffffu, dup) || (orp != totc);

    if (!conflict) {
        #pragma unroll
        for (int i = 0; i < 8; i++)
            g_match[b * Tq + i * 32 + l] = (rmax[i] >= 0.7f) ? rarg[i] : -1;
        return;
    }

    // slow path: exact sequential greedy (value desc, flat-index asc tiebreak)
    #pragma unroll
    for (int i = 0; i < 8; i++) g_match[b * Tq + i * 32 + l] = -1;
    unsigned taken[8] = {0,0,0,0,0,0,0,0};
    for (int it = 0; it < 256; it++) {
        float bv = rmax[0]; int bi = 0;
        #pragma unroll
        for (int i = 1; i < 8; i++) if (rmax[i] > bv) { bv = rmax[i]; bi = i; }
        int brow = bi * 32 + l;
        #pragma unroll
        for (int off = 16; off; off >>= 1) {
            float ov = __shfl_xor_sync(0xffffffffu, bv, off);
            int orow  = __shfl_xor_sync(0xffffffffu, brow, off);
            if (ov > bv || (ov == bv && orow < brow)) { bv = ov; brow = orow; }
        }
        if (bv < 0.7f) break;
        int ol = brow & 31, oi = brow >> 5;
        int d = __shfl_sync(0xffffffffu, rarg[oi], ol);
        taken[d >> 5] |= 1u << (d & 31);
        if (l == ol) { g_match[b * Tq + brow] = d; rmax[oi] = -3.0f; }
        #pragma unroll
        for (int i = 0; i < 8; i++) {
            if (rmax[i] >= 0.7f && rarg[i] == d) {
                int row = i * 32 + l;
                const float* rr = g_C + ((size_t)b * Tq + row) * Nq;
                float best = -2.0f; int arg = 0;
                for (int n = 0; n < 256; n++) {
                    if (taken[n >> 5] & (1u << (n & 31))) continue;
                    float c = rr[n];
                    if (c > best) { best = c; arg = n; }
                }
                rmax[i] = best; rarg[i] = arg;
            }
        }
    }
}

// ---------------------------------------------------------------------------
// Output assembly.
__global__ __launch_bounds__(256) void output_kernel(
    const float* __restrict__ tm, const float* __restrict__ dm,
    const float* __restrict__ tb, const float* __restrict__ db,
    const void* __restrict__ act, const int* __restrict__ age,
    const int* __restrict__ hits, float* __restrict__ out) {
    int blk = blockIdx.x;
    if (blk < Bq * Tq) {
        int b = blk >> 8;
        int m = g_match[blk];
        const float* src = (m >= 0) ? (dm + ((size_t)b * Nq + m) * Dq)
                                    : (tm + (size_t)blk * Dq);
        float4 v = ((const float4*)src)[threadIdx.x];
        ((float4*)(out + (size_t)blk * Dq))[threadIdx.x] = v;
    } else {
        int b = blk - Bq * Tq;
        int t = threadIdx.x;
        int idx = b * Tq + t;
        int m = g_match[idx];
        bool matched = m >= 0;
        int d = matched ? m : 0;
        int s4 = g_stride4;
        bool a = get_active(act, idx, s4);
        int h = hits[idx] + (matched ? 1 : 0);
        bool unm = a && !matched;
        int ag = age[idx];
        int newage = matched ? 0 : (unm ? ag + 1 : ag);
        bool newact = matched ? true : (unm ? (newage <= 10) : a);
        float4 bx = matched ? ((const float4*)db)[b * Nq + d]
                            : ((const float4*)tb)[idx];
        ((float4*)(out + OFF_BOX))[idx] = bx;
        out[OFF_ACT   + idx] = newact ? 1.0f : 0.0f;
        out[OFF_AGE   + idx] = (float)newage;
        out[OFF_HITS  + idx] = (float)h;
        out[OFF_MATCH + idx] = (float)m;
    }
}

// ---------------------------------------------------------------------------
extern "C" void kernel_launch(void* const* d_in, const int* in_sizes, int n_in,
                              void* d_out, int out_size) {
    const float* tm   = (const float*)d_in[0];
    const float* tb   = (const float*)d_in[1];
    const void*  act  = d_in[2];
    const int*   age  = (const int*)d_in[3];
    const int*   hits = (const int*)d_in[4];
    const float* db   = (const float*)d_in[5];
    const float* dm   = (const float*)d_in[6];
    const float* cl   = (const float*)d_in[7];
    float* out = (float*)d_out;

    scores_kernel<<<(Bq*Nq)/4, 128>>>(cl, (const unsigned char*)act, out + OFF_SCORES);
    dim3 g(Nq/128, Tq/128, Bq);
    gemm_cmat_mma<<<g, 256>>>(tm, dm, tb, db, act);
    greedy_kernel<<<Bq, 32>>>();
    output_kernel<<<Bq*Tq + Bq, 256>>>(tm, dm, tb, db, act, age, hits, out);
}

// round 10
// speedup vs baseline: 2.4806x; 1.0050x over previous
#include <cuda_runtime.h>
#include <math.h>
#include <stdint.h>

#define Bq 32
#define Tq 256
#define Nq 256
#define Dq 1024
#define Cq 80

// output layout (float32, tuple order)
#define OFF_BOX    (Bq*Tq*Dq)
#define OFF_ACT    (OFF_BOX + Bq*Tq*4)
#define OFF_AGE    (OFF_ACT + Bq*Tq)
#define OFF_HITS   (OFF_AGE + Bq*Tq)
#define OFF_MATCH  (OFF_HITS + Bq*Tq)
#define OFF_SCORES (OFF_MATCH + Bq*Tq)

// scratch
__device__ float  g_C[Bq*Tq*Nq];      // cost matrix (fallback path)
__device__ float2 g_rmax[Bq*Tq*2];    // per-(row, colTile) max/arg
__device__ int    g_match[Bq*Tq];
__device__ int    g_stride4;

// ---------------------------------------------------------------------------
__device__ __forceinline__ bool get_active(const void* act, int idx, int s4) {
    if (s4) return ((const int*)act)[idx] != 0;
    return ((const unsigned char*)act)[idx] != 0;
}

// bf16x2 mma: D(f32x4) += A(bf16 m16k16) * B(bf16 k16n8)
__device__ __forceinline__ void mma16816(float* d, const uint32_t* a, const uint32_t* b) {
    asm volatile(
        "mma.sync.aligned.m16n8k16.row.col.f32.bf16.bf16.f32 "
        "{%0,%1,%2,%3}, {%4,%5,%6,%7}, {%8,%9}, {%0,%1,%2,%3};"
        : "+f"(d[0]), "+f"(d[1]), "+f"(d[2]), "+f"(d[3])
        : "r"(a[0]), "r"(a[1]), "r"(a[2]), "r"(a[3]), "r"(b[0]), "r"(b[1]));
}

// fp32 float4 -> (hi bf16x2 pair, lo bf16x2 pair)
__device__ __forceinline__ void split4(float4 v, uint32_t& h0, uint32_t& h1,
                                       uint32_t& l0, uint32_t& l1) {
    asm("cvt.rn.bf16x2.f32 %0, %1, %2;" : "=r"(h0) : "f"(v.y), "f"(v.x));
    asm("cvt.rn.bf16x2.f32 %0, %1, %2;" : "=r"(h1) : "f"(v.w), "f"(v.z));
    float rx = v.x - __uint_as_float(h0 << 16);
    float ry = v.y - __uint_as_float(h0 & 0xFFFF0000u);
    float rz = v.z - __uint_as_float(h1 << 16);
    float rw = v.w - __uint_as_float(h1 & 0xFFFF0000u);
    asm("cvt.rn.bf16x2.f32 %0, %1, %2;" : "=r"(l0) : "f"(ry), "f"(rx));
    asm("cvt.rn.bf16x2.f32 %0, %1, %2;" : "=r"(l1) : "f"(rw), "f"(rz));
}

// ---------------------------------------------------------------------------
// scores + active-width probe
__global__ __launch_bounds__(128) void scores_kernel(const float* __restrict__ logits,
                                                     const unsigned char* __restrict__ act,
                                                     float* __restrict__ out) {
    if (blockIdx.x == 0 && threadIdx.x == 0) {
        int ones = 0;
        for (int i = 0; i < 64; i++) ones += (act[4 * i + 1] != 0);
        g_stride4 = (ones > 8) ? 0 : 1;
    }
    int row = blockIdx.x * 4 + (threadIdx.x >> 5);
    int lane = threadIdx.x & 31;
    const float* p = logits + (size_t)row * Cq;
    float a = p[lane];
    float b = p[lane + 32];
    bool hasc = (lane + 64) < Cq;
    float c = hasc ? p[lane + 64] : -INFINITY;
    float m = fmaxf(a, fmaxf(b, c));
    #pragma unroll
    for (int off = 16; off; off >>= 1) m = fmaxf(m, __shfl_xor_sync(0xffffffffu, m, off));
    float s = expf(a - m) + expf(b - m) + (hasc ? expf(c - m) : 0.0f);
    #pragma unroll
    for (int off = 16; off; off >>= 1) s += __shfl_xor_sync(0xffffffffu, s, off);
    if (lane == 0) out[row] = 1.0f / s;
}

// ---------------------------------------------------------------------------
// HMMA (mma.sync bf16) 3-pass split GEMM, double-buffered SMEM, one barrier
// per chunk. 128x128 tile per CTA, K chunks of 32, 8 warps 4x2.
#define KST 20          // smem row stride in uint32 (conflict-free)
#define STGW (128*KST)  // words per sub-tile
#define STAGE (4*STGW)  // words per stage (Ahi, Alo, Bhi, Blo)

__global__ __launch_bounds__(256) void gemm_cmat_mma(
    const float* __restrict__ tm, const float* __restrict__ dm,
    const float* __restrict__ tb, const float* __restrict__ db,
    const void* __restrict__ act) {
    extern __shared__ uint32_t dyn[];
    __shared__ float s_an[128], s_bn[128], s_dinv[128];
    __shared__ float4 s_tbox[128], s_dbox[128];
    __shared__ float2 s_rmv[2][128];

    int tid = threadIdx.x;
    int b = blockIdx.z, rowBase = blockIdx.y * 128, colBase = blockIdx.x * 128;

    int r = tid >> 1, h = tid & 1;           // load role: row 0..127, k-half
    const float* aP = tm + ((size_t)(b * Tq + rowBase + r)) * Dq + h * 16;
    const float* bP = dm + ((size_t)(b * Nq + colBase + r)) * Dq + h * 16;

    int lane = tid & 31, wid = tid >> 5;
    int wm = wid & 3, wn = wid >> 2;         // warp tile: rows wm*32+, cols wn*64+
    int qrow = lane >> 2, qk = lane & 3;

    float acc[2][8][4];
    #pragma unroll
    for (int mi = 0; mi < 2; mi++)
        #pragma unroll
        for (int ni = 0; ni < 8; ni++)
            #pragma unroll
            for (int q = 0; q < 4; q++) acc[mi][ni][q] = 0.0f;

    float asum = 0.f, bsum = 0.f;
    int kp = r * KST + h * 8;

    float4 ra[4], rb[4];
    #pragma unroll
    for (int q = 0; q < 4; q++) {
        ra[q] = *(const float4*)(aP + q * 4);
        rb[q] = *(const float4*)(bP + q * 4);
    }
    // prologue: convert+store chunk 0 into stage 0
    {
        uint32_t* st = dyn;
        #pragma unroll
        for (int q = 0; q < 4; q++) {
            float4 v = ra[q];
            asum += v.x*v.x + v.y*v.y + v.z*v.z + v.w*v.w;
            uint32_t h0,h1,l0,l1; split4(v, h0,h1,l0,l1);
            st[kp + q*2] = h0;           st[kp + q*2 + 1] = h1;
            st[STGW + kp + q*2] = l0;    st[STGW + kp + q*2 + 1] = l1;
            v = rb[q];
            bsum += v.x*v.x + v.y*v.y + v.z*v.z + v.w*v.w;
            split4(v, h0,h1,l0,l1);
            st[2*STGW + kp + q*2] = h0;  st[2*STGW + kp + q*2 + 1] = h1;
            st[3*STGW + kp + q*2] = l0;  st[3*STGW + kp + q*2 + 1] = l1;
        }
    }
    __syncthreads();

    for (int c = 0; c < 32; c++) {
        // prefetch chunk c+1 from global (latency hidden under MMA phase)
        if (c < 31) {
            int k0 = (c + 1) * 32;
            #pragma unroll
            for (int q = 0; q < 4; q++) {
                ra[q] = *(const float4*)(aP + k0 + q * 4);
                rb[q] = *(const float4*)(bP + k0 + q * 4);
            }
        }
        // MMA on stage c&1
        {
            const uint32_t* As_hi = dyn + (c & 1) * STAGE;
            const uint32_t* As_lo = As_hi + STGW;
            const uint32_t* Bs_hi = As_hi + 2*STGW;
            const uint32_t* Bs_lo = As_hi + 3*STGW;
            #pragma unroll
            for (int s = 0; s < 2; s++) {
                int kb = s * 8 + qk;
                uint32_t ah[2][4], al[2][4], bh[8][2], bl[8][2];
                #pragma unroll
                for (int mi = 0; mi < 2; mi++) {
                    int row = wm * 32 + mi * 16 + qrow;
                    ah[mi][0] = As_hi[row*KST + kb];       ah[mi][1] = As_hi[(row+8)*KST + kb];
                    ah[mi][2] = As_hi[row*KST + kb + 4];   ah[mi][3] = As_hi[(row+8)*KST + kb + 4];
                    al[mi][0] = As_lo[row*KST + kb];       al[mi][1] = As_lo[(row+8)*KST + kb];
                    al[mi][2] = As_lo[row*KST + kb + 4];   al[mi][3] = As_lo[(row+8)*KST + kb + 4];
                }
                #pragma unroll
                for (int ni = 0; ni < 8; ni++) {
                    int col = wn * 64 + ni * 8 + qrow;
                    bh[ni][0] = Bs_hi[col*KST + kb];  bh[ni][1] = Bs_hi[col*KST + kb + 4];
                    bl[ni][0] = Bs_lo[col*KST + kb];  bl[ni][1] = Bs_lo[col*KST + kb + 4];
                }
                #pragma unroll
                for (int mi = 0; mi < 2; mi++)
                    #pragma unroll
                    for (int ni = 0; ni < 8; ni++) {
                        mma16816(acc[mi][ni], ah[mi], bh[ni]);
                        mma16816(acc[mi][ni], ah[mi], bl[ni]);
                        mma16816(acc[mi][ni], al[mi], bh[ni]);
                    }
            }
        }
        // convert+store chunk c+1 into the other stage (its previous MMA done
        // at the barrier ending iteration c-1)
        if (c < 31) {
            uint32_t* st = dyn + ((c + 1) & 1) * STAGE;
            #pragma unroll
            for (int q = 0; q < 4; q++) {
                float4 v = ra[q];
                asum += v.x*v.x + v.y*v.y + v.z*v.z + v.w*v.w;
                uint32_t h0,h1,l0,l1; split4(v, h0,h1,l0,l1);
                st[kp + q*2] = h0;           st[kp + q*2 + 1] = h1;
                st[STGW + kp + q*2] = l0;    st[STGW + kp + q*2 + 1] = l1;
                v = rb[q];
                bsum += v.x*v.x + v.y*v.y + v.z*v.z + v.w*v.w;
                split4(v, h0,h1,l0,l1);
                st[2*STGW + kp + q*2] = h0;  st[2*STGW + kp + q*2 + 1] = h1;
                st[3*STGW + kp + q*2] = l0;  st[3*STGW + kp + q*2 + 1] = l1;
            }
        }
        __syncthreads();
    }

    // norms: partner thread (tid^1) holds the other k-half of the same row
    asum += __shfl_xor_sync(0xffffffffu, asum, 1);
    bsum += __shfl_xor_sync(0xffffffffu, bsum, 1);
    if ((tid & 1) == 0) { s_an[r] = asum; s_bn[r] = bsum; }
    if (tid < 128) {
        s_tbox[tid] = ((const float4*)tb)[b * Tq + rowBase + tid];
        s_dbox[tid] = ((const float4*)db)[b * Nq + colBase + tid];
    }
    __syncthreads();
    if (tid < 128) s_dinv[tid] = 1.0f / fmaxf(sqrtf(s_bn[tid]), 1e-12f);
    __syncthreads();

    int s4 = g_stride4;
    #pragma unroll
    for (int mi = 0; mi < 2; mi++) {
        #pragma unroll
        for (int half = 0; half < 2; half++) {
            int lr = wm * 32 + mi * 16 + half * 8 + qrow;
            int gt = rowBase + lr;
            float ti = 1.0f / fmaxf(sqrtf(s_an[lr]), 1e-12f);
            float4 tbx = s_tbox[lr];
            bool aa = get_active(act, b * Tq + gt, s4);
            float tx1 = tbx.x - 0.5f * tbx.z, tx2 = tbx.x + 0.5f * tbx.z;
            float ty1 = tbx.y - 0.5f * tbx.w, ty2 = tbx.y + 0.5f * tbx.w;
            float tarea = tbx.z * tbx.w;
            float best = -2.0f; int barg = 0;
            float* dst = g_C + ((size_t)(b * Tq + gt)) * Nq + colBase;
            #pragma unroll
            for (int ni = 0; ni < 8; ni++) {
                int lc = wn * 64 + ni * 8 + qk * 2;
                float2 o;
                #pragma unroll
                for (int j = 0; j < 2; j++) {
                    float dot = acc[mi][ni][half * 2 + j];
                    float4 dv = s_dbox[lc + j];
                    float dx1 = dv.x - 0.5f * dv.z, dx2 = dv.x + 0.5f * dv.z;
                    float dy1 = dv.y - 0.5f * dv.w, dy2 = dv.y + 0.5f * dv.w;
                    float iw = fmaxf(fminf(tx2, dx2) - fmaxf(tx1, dx1), 0.0f);
                    float ih = fmaxf(fminf(ty2, dy2) - fmaxf(ty1, dy1), 0.0f);
                    float inter = iw * ih;
                    float uni = tarea + dv.z * dv.w - inter;
                    float iou = inter / (uni + 1e-6f);
                    float cv = 0.7f * (dot * ti * s_dinv[lc + j]) + 0.3f * iou;
                    cv = aa ? cv : -1.0f;
                    if (cv > best) { best = cv; barg = lc + j; }
                    (&o.x)[j] = cv;
                }
                *(float2*)(dst + lc) = o;
            }
            // row-max reduce over the 4 lanes sharing this row (vary qk)
            #pragma unroll
            for (int off = 1; off <= 2; off <<= 1) {
                float ov = __shfl_xor_sync(0xffffffffu, best, off);
                int   oa = __shfl_xor_sync(0xffffffffu, barg, off);
                if (ov > best || (ov == best && oa < barg)) { best = ov; barg = oa; }
            }
            if (qk == 0) s_rmv[wn][lr] = make_float2(best, __int_as_float(colBase + barg));
        }
    }
    __syncthreads();
    if (tid < 128) {
        float2 m0 = s_rmv[0][tid], m1 = s_rmv[1][tid];
        float2 mm = (m1.x > m0.x) ? m1 : m0;
        g_rmax[(b * Tq + rowBase + tid) * 2 + blockIdx.x] = mm;
    }
}

// ---------------------------------------------------------------------------
// Greedy matching, one warp per batch. Fast path reads g_rmax only.
__global__ __launch_bounds__(32) void greedy_kernel() {
    int b = blockIdx.x;
    int l = threadIdx.x;

    float rmax[8]; int rarg[8];
    #pragma unroll
    for (int i = 0; i < 8; i++) {
        int row = i * 32 + l;
        float2 m0 = g_rmax[(b * Tq + row) * 2 + 0];
        float2 m1 = g_rmax[(b * Tq + row) * 2 + 1];
        float v = m0.x; int a = __float_as_int(m0.y);
        if (m1.x > v) { v = m1.x; a = __float_as_int(m1.y); }
        rmax[i] = v; rarg[i] = a;
    }

    // fast-path distinctness check
    unsigned cm[8] = {0,0,0,0,0,0,0,0};
    int cnt = 0;
    #pragma unroll
    for (int i = 0; i < 8; i++)
        if (rmax[i] >= 0.7f) { cnt++; cm[rarg[i] >> 5] |= 1u << (rarg[i] & 31); }
    int lpop = 0;
    #pragma unroll
    for (int w = 0; w < 8; w++) lpop += __popc(cm[w]);
    int totc = __reduce_add_sync(0xffffffffu, cnt);
    int orp = 0;
    #pragma unroll
    for (int w = 0; w < 8; w++) orp += __popc(__reduce_or_sync(0xffffffffu, cm[w]));
    bool dup = (lpop != cnt);
    bool conflict = __any_sync(0xffffffffu, dup) || (orp != totc);

    if (!conflict) {
        #pragma unroll
        for (int i = 0; i < 8; i++)
            g_match[b * Tq + i * 32 + l] = (rmax[i] >= 0.7f) ? rarg[i] : -1;
        return;
    }

    // slow path: exact sequential greedy (value desc, flat-index asc tiebreak)
    #pragma unroll
    for (int i = 0; i < 8; i++) g_match[b * Tq + i * 32 + l] = -1;
    unsigned taken[8] = {0,0,0,0,0,0,0,0};
    for (int it = 0; it < 256; it++) {
        float bv = rmax[0]; int bi = 0;
        #pragma unroll
        for (int i = 1; i < 8; i++) if (rmax[i] > bv) { bv = rmax[i]; bi = i; }
        int brow = bi * 32 + l;
        #pragma unroll
        for (int off = 16; off; off >>= 1) {
            float ov = __shfl_xor_sync(0xffffffffu, bv, off);
            int orow  = __shfl_xor_sync(0xffffffffu, brow, off);
            if (ov > bv || (ov == bv && orow < brow)) { bv = ov; brow = orow; }
        }
        if (bv < 0.7f) break;
        int ol = brow & 31, oi = brow >> 5;
        int d = __shfl_sync(0xffffffffu, rarg[oi], ol);
        taken[d >> 5] |= 1u << (d & 31);
        if (l == ol) { g_match[b * Tq + brow] = d; rmax[oi] = -3.0f; }
        #pragma unroll
        for (int i = 0; i < 8; i++) {
            if (rmax[i] >= 0.7f && rarg[i] == d) {
                int row = i * 32 + l;
                const float* rr = g_C + ((size_t)b * Tq + row) * Nq;
                float best = -2.0f; int arg = 0;
                for (int n = 0; n < 256; n++) {
                    if (taken[n >> 5] & (1u << (n & 31))) continue;
                    float c = rr[n];
                    if (c > best) { best = c; arg = n; }
                }
                rmax[i] = best; rarg[i] = arg;
            }
        }
    }
}

// ---------------------------------------------------------------------------
// Output assembly. Memory blocks handle 2 rows each with 2 independent
// LDG.128 per thread (MLP=2).
__global__ __launch_bounds__(256) void output_kernel(
    const float* __restrict__ tm, const float* __restrict__ dm,
    const float* __restrict__ tb, const float* __restrict__ db,
    const void* __restrict__ act, const int* __restrict__ age,
    const int* __restrict__ hits, float* __restrict__ out) {
    int blk = blockIdx.x;
    if (blk < Bq * Tq / 2) {
        int row = blk * 2 + (threadIdx.x >> 7);
        int b = row >> 8;
        int m = g_match[row];
        const float* src = (m >= 0) ? (dm + ((size_t)b * Nq + m) * Dq)
                                    : (tm + (size_t)row * Dq);
        int j = threadIdx.x & 127;
        float4 v0 = ((const float4*)src)[j];
        float4 v1 = ((const float4*)src)[j + 128];
        float4* dst = (float4*)(out + (size_t)row * Dq);
        dst[j] = v0;
        dst[j + 128] = v1;
    } else {
        int b = blk - Bq * Tq / 2;
        int t = threadIdx.x;
        int idx = b * Tq + t;
        int m = g_match[idx];
        bool matched = m >= 0;
        int d = matched ? m : 0;
        int s4 = g_stride4;
        bool a = get_active(act, idx, s4);
        int h = hits[idx] + (matched ? 1 : 0);
        bool unm = a && !matched;
        int ag = age[idx];
        int newage = matched ? 0 : (unm ? ag + 1 : ag);
        bool newact = matched ? true : (unm ? (newage <= 10) : a);
        float4 bx = matched ? ((const float4*)db)[b * Nq + d]
                            : ((const float4*)tb)[idx];
        ((float4*)(out + OFF_BOX))[idx] = bx;
        out[OFF_ACT   + idx] = newact ? 1.0f : 0.0f;
        out[OFF_AGE   + idx] = (float)newage;
        out[OFF_HITS  + idx] = (float)h;
        out[OFF_MATCH + idx] = (float)m;
    }
}

// ---------------------------------------------------------------------------
extern "C" void kernel_launch(void* const* d_in, const int* in_sizes, int n_in,
                              void* d_out, int out_size) {
    const float* tm   = (const float*)d_in[0];
    const float* tb   = (const float*)d_in[1];
    const void*  act  = d_in[2];
    const int*   age  = (const int*)d_in[3];
    const int*   hits = (const int*)d_in[4];
    const float* db   = (const float*)d_in[5];
    const float* dm   = (const float*)d_in[6];
    const float* cl   = (const float*)d_in[7];
    float* out = (float*)d_out;

    static int cfg_done = 0;
    int smem_bytes = 2 * STAGE * 4;   // 81920
    if (!cfg_done) {
        cudaFuncSetAttribute(gemm_cmat_mma,
                             cudaFuncAttributeMaxDynamicSharedMemorySize, smem_bytes);
        cfg_done = 1;
    }

    scores_kernel<<<(Bq*Nq)/4, 128>>>(cl, (const unsigned char*)act, out + OFF_SCORES);
    dim3 g(Nq/128, Tq/128, Bq);
    gemm_cmat_mma<<<g, 256, smem_bytes>>>(tm, dm, tb, db, act);
    greedy_kernel<<<Bq, 32>>>();
    output_kernel<<<Bq*Tq/2 + Bq, 256>>>(tm, dm, tb, db, act, age, hits, out);
}

// round 11
// speedup vs baseline: 2.5849x; 1.0421x over previous
#include <cuda_runtime.h>
#include <math.h>
#include <stdint.h>

#define Bq 32
#define Tq 256
#define Nq 256
#define Dq 1024
#define Cq 80

// output layout (float32, tuple order)
#define OFF_BOX    (Bq*Tq*Dq)
#define OFF_ACT    (OFF_BOX + Bq*Tq*4)
#define OFF_AGE    (OFF_ACT + Bq*Tq)
#define OFF_HITS   (OFF_AGE + Bq*Tq)
#define OFF_MATCH  (OFF_HITS + Bq*Tq)
#define OFF_SCORES (OFF_MATCH + Bq*Tq)

// scratch
__device__ float  g_C[Bq*Tq*Nq];      // cost matrix (fallback path)
__device__ float2 g_rmax[Bq*Tq*2];    // per-(row, colTile) max/arg
__device__ int    g_match[Bq*Tq];

// ---------------------------------------------------------------------------
// active-storage-width probe, warp-converged (byte offsets 1 mod 4 of the
// first 64 elements: uint8 bools ~90% nonzero; int32/float32 byte1 always 0)
__device__ __forceinline__ int probe_s4(const unsigned char* __restrict__ act) {
    int lane = threadIdx.x & 31;
    int o1 = (act[4 * lane + 1] != 0) ? 1 : 0;
    int o2 = (act[4 * (lane + 32) + 1] != 0) ? 1 : 0;
    int ones = __popc(__ballot_sync(0xffffffffu, o1)) +
               __popc(__ballot_sync(0xffffffffu, o2));
    return (ones > 8) ? 0 : 1;
}

__device__ __forceinline__ bool get_active(const void* act, int idx, int s4) {
    if (s4) return ((const int*)act)[idx] != 0;
    return ((const unsigned char*)act)[idx] != 0;
}

__device__ __forceinline__ uint32_t smem_u32(const void* p) {
    uint32_t a;
    asm("{ .reg .u64 t; cvta.to.shared.u64 t, %1; cvt.u32.u64 %0, t; }" : "=r"(a) : "l"(p));
    return a;
}

// bf16x2 mma: D(f32x4) += A(bf16 m16k16) * B(bf16 k16n8)
__device__ __forceinline__ void mma16816(float* d, const uint32_t* a, const uint32_t* b) {
    asm volatile(
        "mma.sync.aligned.m16n8k16.row.col.f32.bf16.bf16.f32 "
        "{%0,%1,%2,%3}, {%4,%5,%6,%7}, {%8,%9}, {%0,%1,%2,%3};"
        : "+f"(d[0]), "+f"(d[1]), "+f"(d[2]), "+f"(d[3])
        : "r"(a[0]), "r"(a[1]), "r"(a[2]), "r"(a[3]), "r"(b[0]), "r"(b[1]));
}

__device__ __forceinline__ void ldsm4(uint32_t* r, uint32_t addr) {
    asm volatile("ldmatrix.sync.aligned.m8n8.x4.shared.b16 {%0,%1,%2,%3}, [%4];"
                 : "=r"(r[0]), "=r"(r[1]), "=r"(r[2]), "=r"(r[3]) : "r"(addr));
}

// fp32 float4 -> (hi bf16x2 pair, lo bf16x2 pair)
__device__ __forceinline__ void split4(float4 v, uint32_t& h0, uint32_t& h1,
                                       uint32_t& l0, uint32_t& l1) {
    asm("cvt.rn.bf16x2.f32 %0, %1, %2;" : "=r"(h0) : "f"(v.y), "f"(v.x));
    asm("cvt.rn.bf16x2.f32 %0, %1, %2;" : "=r"(h1) : "f"(v.w), "f"(v.z));
    float rx = v.x - __uint_as_float(h0 << 16);
    float ry = v.y - __uint_as_float(h0 & 0xFFFF0000u);
    float rz = v.z - __uint_as_float(h1 << 16);
    float rw = v.w - __uint_as_float(h1 & 0xFFFF0000u);
    asm("cvt.rn.bf16x2.f32 %0, %1, %2;" : "=r"(l0) : "f"(ry), "f"(rx));
    asm("cvt.rn.bf16x2.f32 %0, %1, %2;" : "=r"(l1) : "f"(rw), "f"(rz));
}

// ---------------------------------------------------------------------------
// HMMA (mma.sync bf16) 3-pass split GEMM, double-buffered SMEM, ldmatrix
// fragment loads. 128x128 tile per CTA, K chunks of 32, 8 warps 4x2.
#define KST 20          // smem row stride in uint32 (80 B, LDSM conflict-free)
#define STGW (128*KST)  // words per sub-tile
#define STAGE (4*STGW)  // words per stage (Ahi, Alo, Bhi, Blo)

__global__ __launch_bounds__(256) void gemm_cmat_mma(
    const float* __restrict__ tm, const float* __restrict__ dm,
    const float* __restrict__ tb, const float* __restrict__ db,
    const void* __restrict__ act) {
    extern __shared__ uint32_t dyn[];
    __shared__ float s_an[128], s_bn[128], s_dinv[128];
    __shared__ float4 s_tbox[128], s_dbox[128];
    __shared__ float2 s_rmv[2][128];

    int tid = threadIdx.x;
    int b = blockIdx.z, rowBase = blockIdx.y * 128, colBase = blockIdx.x * 128;
    int s4 = probe_s4((const unsigned char*)act);

    int r = tid >> 1, h = tid & 1;           // load role: row 0..127, k-half
    const float* aP = tm + ((size_t)(b * Tq + rowBase + r)) * Dq + h * 16;
    const float* bP = dm + ((size_t)(b * Nq + colBase + r)) * Dq + h * 16;

    int lane = tid & 31, wid = tid >> 5;
    int wm = wid & 3, wn = wid >> 2;         // warp tile: rows wm*32+, cols wn*64+
    int qrow = lane >> 2, qk = lane & 3;

    // ldmatrix per-lane base addresses (byte offsets into a stage)
    uint32_t sm0 = smem_u32(dyn);
    uint32_t aAddr = sm0 + (uint32_t)(wm * 32 + (lane & 15)) * 80u + (uint32_t)(lane >> 4) * 16u;
    uint32_t bAddr = sm0 + (uint32_t)(2 * STGW) * 4u
                   + (uint32_t)(wn * 64 + ((lane >> 4) * 8) + (lane & 7)) * 80u
                   + (uint32_t)((lane >> 3) & 1) * 16u;

    float acc[2][8][4];
    #pragma unroll
    for (int mi = 0; mi < 2; mi++)
        #pragma unroll
        for (int ni = 0; ni < 8; ni++)
            #pragma unroll
            for (int q = 0; q < 4; q++) acc[mi][ni][q] = 0.0f;

    float asum = 0.f, bsum = 0.f;
    int kp = r * KST + h * 8;

    float4 ra[4], rb[4];
    #pragma unroll
    for (int q = 0; q < 4; q++) {
        ra[q] = *(const float4*)(aP + q * 4);
        rb[q] = *(const float4*)(bP + q * 4);
    }
    // prologue: convert+store chunk 0 into stage 0
    {
        uint32_t* st = dyn;
        #pragma unroll
        for (int q = 0; q < 4; q++) {
            float4 v = ra[q];
            asum += v.x*v.x + v.y*v.y + v.z*v.z + v.w*v.w;
            uint32_t h0,h1,l0,l1; split4(v, h0,h1,l0,l1);
            st[kp + q*2] = h0;           st[kp + q*2 + 1] = h1;
            st[STGW + kp + q*2] = l0;    st[STGW + kp + q*2 + 1] = l1;
            v = rb[q];
            bsum += v.x*v.x + v.y*v.y + v.z*v.z + v.w*v.w;
            split4(v, h0,h1,l0,l1);
            st[2*STGW + kp + q*2] = h0;  st[2*STGW + kp + q*2 + 1] = h1;
            st[3*STGW + kp + q*2] = l0;  st[3*STGW + kp + q*2 + 1] = l1;
        }
    }
    __syncthreads();

    for (int c = 0; c < 32; c++) {
        // prefetch chunk c+1 from global
        if (c < 31) {
            int k0 = (c + 1) * 32;
            #pragma unroll
            for (int q = 0; q < 4; q++) {
                ra[q] = *(const float4*)(aP + k0 + q * 4);
                rb[q] = *(const float4*)(bP + k0 + q * 4);
            }
        }
        // MMA on stage c&1 via ldmatrix
        {
            uint32_t stg = (uint32_t)(c & 1) * (STAGE * 4u);
            #pragma unroll
            for (int s = 0; s < 2; s++) {
                uint32_t ko = stg + (uint32_t)s * 32u;
                uint32_t ah[2][4], al[2][4], bh[8][2], bl[8][2];
                #pragma unroll
                for (int mi = 0; mi < 2; mi++) {
                    ldsm4(ah[mi], aAddr + ko + (uint32_t)(mi * 16) * 80u);
                    ldsm4(al[mi], aAddr + ko + (uint32_t)(mi * 16) * 80u + STGW * 4u);
                }
                #pragma unroll
                for (int pr = 0; pr < 4; pr++) {
                    uint32_t t4[4];
                    ldsm4(t4, bAddr + ko + (uint32_t)(pr * 16) * 80u);
                    bh[2*pr][0] = t4[0]; bh[2*pr][1] = t4[1];
                    bh[2*pr+1][0] = t4[2]; bh[2*pr+1][1] = t4[3];
                    ldsm4(t4, bAddr + ko + (uint32_t)(pr * 16) * 80u + STGW * 4u);
                    bl[2*pr][0] = t4[0]; bl[2*pr][1] = t4[1];
                    bl[2*pr+1][0] = t4[2]; bl[2*pr+1][1] = t4[3];
                }
                #pragma unroll
                for (int mi = 0; mi < 2; mi++)
                    #pragma unroll
                    for (int ni = 0; ni < 8; ni++) {
                        mma16816(acc[mi][ni], ah[mi], bh[ni]);
                        mma16816(acc[mi][ni], ah[mi], bl[ni]);
                        mma16816(acc[mi][ni], al[mi], bh[ni]);
                    }
            }
        }
        // convert+store chunk c+1 into the other stage
        if (c < 31) {
            uint32_t* st = dyn + ((c + 1) & 1) * STAGE;
            #pragma unroll
            for (int q = 0; q < 4; q++) {
                float4 v = ra[q];
                asum += v.x*v.x + v.y*v.y + v.z*v.z + v.w*v.w;
                uint32_t h0,h1,l0,l1; split4(v, h0,h1,l0,l1);
                st[kp + q*2] = h0;           st[kp + q*2 + 1] = h1;
                st[STGW + kp + q*2] = l0;    st[STGW + kp + q*2 + 1] = l1;
                v = rb[q];
                bsum += v.x*v.x + v.y*v.y + v.z*v.z + v.w*v.w;
                split4(v, h0,h1,l0,l1);
                st[2*STGW + kp + q*2] = h0;  st[2*STGW + kp + q*2 + 1] = h1;
                st[3*STGW + kp + q*2] = l0;  st[3*STGW + kp + q*2 + 1] = l1;
            }
        }
        __syncthreads();
    }

    // norms: partner thread (tid^1) holds the other k-half of the same row
    asum += __shfl_xor_sync(0xffffffffu, asum, 1);
    bsum += __shfl_xor_sync(0xffffffffu, bsum, 1);
    if ((tid & 1) == 0) { s_an[r] = asum; s_bn[r] = bsum; }
    if (tid < 128) {
        s_tbox[tid] = ((const float4*)tb)[b * Tq + rowBase + tid];
        s_dbox[tid] = ((const float4*)db)[b * Nq + colBase + tid];
    }
    __syncthreads();
    if (tid < 128) s_dinv[tid] = 1.0f / fmaxf(sqrtf(s_bn[tid]), 1e-12f);
    __syncthreads();

    #pragma unroll
    for (int mi = 0; mi < 2; mi++) {
        #pragma unroll
        for (int half = 0; half < 2; half++) {
            int lr = wm * 32 + mi * 16 + half * 8 + qrow;
            int gt = rowBase + lr;
            float ti = 1.0f / fmaxf(sqrtf(s_an[lr]), 1e-12f);
            float4 tbx = s_tbox[lr];
            bool aa = get_active(act, b * Tq + gt, s4);
            float tx1 = tbx.x - 0.5f * tbx.z, tx2 = tbx.x + 0.5f * tbx.z;
            float ty1 = tbx.y - 0.5f * tbx.w, ty2 = tbx.y + 0.5f * tbx.w;
            float tarea = tbx.z * tbx.w;
            float best = -2.0f; int barg = 0;
            float* dst = g_C + ((size_t)(b * Tq + gt)) * Nq + colBase;
            #pragma unroll
            for (int ni = 0; ni < 8; ni++) {
                int lc = wn * 64 + ni * 8 + qk * 2;
                float2 o;
                #pragma unroll
                for (int j = 0; j < 2; j++) {
                    float dot = acc[mi][ni][half * 2 + j];
                    float4 dv = s_dbox[lc + j];
                    float dx1 = dv.x - 0.5f * dv.z, dx2 = dv.x + 0.5f * dv.z;
                    float dy1 = dv.y - 0.5f * dv.w, dy2 = dv.y + 0.5f * dv.w;
                    float iw = fmaxf(fminf(tx2, dx2) - fmaxf(tx1, dx1), 0.0f);
                    float ih = fmaxf(fminf(ty2, dy2) - fmaxf(ty1, dy1), 0.0f);
                    float inter = iw * ih;
                    float uni = tarea + dv.z * dv.w - inter;
                    float iou = inter / (uni + 1e-6f);
                    float cv = 0.7f * (dot * ti * s_dinv[lc + j]) + 0.3f * iou;
                    cv = aa ? cv : -1.0f;
                    if (cv > best) { best = cv; barg = lc + j; }
                    (&o.x)[j] = cv;
                }
                *(float2*)(dst + lc) = o;
            }
            // row-max reduce over the 4 lanes sharing this row (vary qk)
            #pragma unroll
            for (int off = 1; off <= 2; off <<= 1) {
                float ov = __shfl_xor_sync(0xffffffffu, best, off);
                int   oa = __shfl_xor_sync(0xffffffffu, barg, off);
                if (ov > best || (ov == best && oa < barg)) { best = ov; barg = oa; }
            }
            if (qk == 0) s_rmv[wn][lr] = make_float2(best, __int_as_float(colBase + barg));
        }
    }
    __syncthreads();
    if (tid < 128) {
        float2 m0 = s_rmv[0][tid], m1 = s_rmv[1][tid];
        float2 mm = (m1.x > m0.x) ? m1 : m0;
        g_rmax[(b * Tq + rowBase + tid) * 2 + blockIdx.x] = mm;
    }
}

// ---------------------------------------------------------------------------
// Greedy matching, one warp per batch. Fast path reads g_rmax only.
__global__ __launch_bounds__(32) void greedy_kernel() {
    int b = blockIdx.x;
    int l = threadIdx.x;

    float rmax[8]; int rarg[8];
    #pragma unroll
    for (int i = 0; i < 8; i++) {
        int row = i * 32 + l;
        float2 m0 = g_rmax[(b * Tq + row) * 2 + 0];
        float2 m1 = g_rmax[(b * Tq + row) * 2 + 1];
        float v = m0.x; int a = __float_as_int(m0.y);
        if (m1.x > v) { v = m1.x; a = __float_as_int(m1.y); }
        rmax[i] = v; rarg[i] = a;
    }

    // fast-path distinctness check
    unsigned cm[8] = {0,0,0,0,0,0,0,0};
    int cnt = 0;
    #pragma unroll
    for (int i = 0; i < 8; i++)
        if (rmax[i] >= 0.7f) { cnt++; cm[rarg[i] >> 5] |= 1u << (rarg[i] & 31); }
    int lpop = 0;
    #pragma unroll
    for (int w = 0; w < 8; w++) lpop += __popc(cm[w]);
    int totc = __reduce_add_sync(0xffffffffu, cnt);
    int orp = 0;
    #pragma unroll
    for (int w = 0; w < 8; w++) orp += __popc(__reduce_or_sync(0xffffffffu, cm[w]));
    bool dup = (lpop != cnt);
    bool conflict = __any_sync(0xffffffffu, dup) || (orp != totc);

    if (!conflict) {
        #pragma unroll
        for (int i = 0; i < 8; i++)
            g_match[b * Tq + i * 32 + l] = (rmax[i] >= 0.7f) ? rarg[i] : -1;
        return;
    }

    // slow path: exact sequential greedy (value desc, flat-index asc tiebreak)
    #pragma unroll
    for (int i = 0; i < 8; i++) g_match[b * Tq + i * 32 + l] = -1;
    unsigned taken[8] = {0,0,0,0,0,0,0,0};
    for (int it = 0; it < 256; it++) {
        float bv = rmax[0]; int bi = 0;
        #pragma unroll
        for (int i = 1; i < 8; i++) if (rmax[i] > bv) { bv = rmax[i]; bi = i; }
        int brow = bi * 32 + l;
        #pragma unroll
        for (int off = 16; off; off >>= 1) {
            float ov = __shfl_xor_sync(0xffffffffu, bv, off);
            int orow  = __shfl_xor_sync(0xffffffffu, brow, off);
            if (ov > bv || (ov == bv && orow < brow)) { bv = ov; brow = orow; }
        }
        if (bv < 0.7f) break;
        int ol = brow & 31, oi = brow >> 5;
        int d = __shfl_sync(0xffffffffu, rarg[oi], ol);
        taken[d >> 5] |= 1u << (d & 31);
        if (l == ol) { g_match[b * Tq + brow] = d; rmax[oi] = -3.0f; }
        #pragma unroll
        for (int i = 0; i < 8; i++) {
            if (rmax[i] >= 0.7f && rarg[i] == d) {
                int row = i * 32 + l;
                const float* rr = g_C + ((size_t)b * Tq + row) * Nq;
                float best = -2.0f; int arg = 0;
                for (int n = 0; n < 256; n++) {
                    if (taken[n >> 5] & (1u << (n & 31))) continue;
                    float c = rr[n];
                    if (c > best) { best = c; arg = n; }
                }
                rmax[i] = best; rarg[i] = arg;
            }
        }
    }
}

// ---------------------------------------------------------------------------
// Output assembly + scores (fused). Block ranges:
//   [0, NR)            : new_mem gather, 4 rows/block, MLP=4
//   [NR, NR+Bq)        : per-batch scalar state + boxes
//   [NR+Bq, ...)       : softmax-max scores, 8 rows/block (one warp per row)
#define NR (Bq*Tq/4)

__global__ __launch_bounds__(256) void output_kernel(
    const float* __restrict__ tm, const float* __restrict__ dm,
    const float* __restrict__ tb, const float* __restrict__ db,
    const void* __restrict__ act, const int* __restrict__ age,
    const int* __restrict__ hits, const float* __restrict__ logits,
    float* __restrict__ out) {
    int blk = blockIdx.x;
    if (blk < NR) {
        int row = blk * 4 + (threadIdx.x >> 6);
        int b = row >> 8;
        int m = g_match[row];
        const float* src = (m >= 0) ? (dm + ((size_t)b * Nq + m) * Dq)
                                    : (tm + (size_t)row * Dq);
        int j = threadIdx.x & 63;
        float4 v0 = ((const float4*)src)[j];
        float4 v1 = ((const float4*)src)[j + 64];
        float4 v2 = ((const float4*)src)[j + 128];
        float4 v3 = ((const float4*)src)[j + 192];
        float4* dst = (float4*)(out + (size_t)row * Dq);
        dst[j] = v0; dst[j + 64] = v1; dst[j + 128] = v2; dst[j + 192] = v3;
    } else if (blk < NR + Bq) {
        int s4 = probe_s4((const unsigned char*)act);
        int b = blk - NR;
        int t = threadIdx.x;
        int idx = b * Tq + t;
        int m = g_match[idx];
        bool matched = m >= 0;
        int d = matched ? m : 0;
        bool a = get_active(act, idx, s4);
        int h = hits[idx] + (matched ? 1 : 0);
        bool unm = a && !matched;
        int ag = age[idx];
        int newage = matched ? 0 : (unm ? ag + 1 : ag);
        bool newact = matched ? true : (unm ? (newage <= 10) : a);
        float4 bx = matched ? ((const float4*)db)[b * Nq + d]
                            : ((const float4*)tb)[idx];
        ((float4*)(out + OFF_BOX))[idx] = bx;
        out[OFF_ACT   + idx] = newact ? 1.0f : 0.0f;
        out[OFF_AGE   + idx] = (float)newage;
        out[OFF_HITS  + idx] = (float)h;
        out[OFF_MATCH + idx] = (float)m;
    } else {
        int row = (blk - NR - Bq) * 8 + (threadIdx.x >> 5);
        int lane = threadIdx.x & 31;
        const float* p = logits + (size_t)row * Cq;
        float a = p[lane];
        float bb = p[lane + 32];
        bool hasc = (lane + 64) < Cq;
        float c = hasc ? p[lane + 64] : -INFINITY;
        float m = fmaxf(a, fmaxf(bb, c));
        #pragma unroll
        for (int off = 16; off; off >>= 1) m = fmaxf(m, __shfl_xor_sync(0xffffffffu, m, off));
        float s = expf(a - m) + expf(bb - m) + (hasc ? expf(c - m) : 0.0f);
        #pragma unroll
        for (int off = 16; off; off >>= 1) s += __shfl_xor_sync(0xffffffffu, s, off);
        if (lane == 0) out[OFF_SCORES + row] = 1.0f / s;
    }
}

// ---------------------------------------------------------------------------
extern "C" void kernel_launch(void* const* d_in, const int* in_sizes, int n_in,
                              void* d_out, int out_size) {
    const float* tm   = (const float*)d_in[0];
    const float* tb   = (const float*)d_in[1];
    const void*  act  = d_in[2];
    const int*   age  = (const int*)d_in[3];
    const int*   hits = (const int*)d_in[4];
    const float* db   = (const float*)d_in[5];
    const float* dm   = (const float*)d_in[6];
    const float* cl   = (const float*)d_in[7];
    float* out = (float*)d_out;

    static int cfg_done = 0;
    int smem_bytes = 2 * STAGE * 4;   // 81920
    if (!cfg_done) {
        cudaFuncSetAttribute(gemm_cmat_mma,
                             cudaFuncAttributeMaxDynamicSharedMemorySize, smem_bytes);
        cfg_done = 1;
    }

    dim3 g(Nq/128, Tq/128, Bq);
    gemm_cmat_mma<<<g, 256, smem_bytes>>>(tm, dm, tb, db, act);
    greedy_kernel<<<Bq, 32>>>();
    output_kernel<<<NR + Bq + (Bq*Nq)/8, 256>>>(tm, dm, tb, db, act, age, hits, cl, out);
}

// round 14
// speedup vs baseline: 2.5952x; 1.0040x over previous
#include <cuda_runtime.h>
#include <math.h>
#include <stdint.h>

#define Bq 32
#define Tq 256
#define Nq 256
#define Dq 1024
#define Cq 80

// output layout (float32, tuple order)
#define OFF_BOX    (Bq*Tq*Dq)
#define OFF_ACT    (OFF_BOX + Bq*Tq*4)
#define OFF_AGE    (OFF_ACT + Bq*Tq)
#define OFF_HITS   (OFF_AGE + Bq*Tq)
#define OFF_MATCH  (OFF_HITS + Bq*Tq)
#define OFF_SCORES (OFF_MATCH + Bq*Tq)

// scratch
__device__ float  g_C[Bq*Tq*Nq];      // cost matrix (fallback path)
__device__ float2 g_rmax[Bq*Tq*4];    // per-(row, colTile) max/arg
__device__ int    g_match[Bq*Tq];

// ---------------------------------------------------------------------------
// active-storage-width probe, warp-converged
__device__ __forceinline__ int probe_s4(const unsigned char* __restrict__ act) {
    int lane = threadIdx.x & 31;
    int o1 = (act[4 * lane + 1] != 0) ? 1 : 0;
    int o2 = (act[4 * (lane + 32) + 1] != 0) ? 1 : 0;
    int ones = __popc(__ballot_sync(0xffffffffu, o1)) +
               __popc(__ballot_sync(0xffffffffu, o2));
    return (ones > 8) ? 0 : 1;
}

__device__ __forceinline__ bool get_active(const void* act, int idx, int s4) {
    if (s4) return ((const int*)act)[idx] != 0;
    return ((const unsigned char*)act)[idx] != 0;
}

__device__ __forceinline__ uint32_t smem_u32(const void* p) {
    uint32_t a;
    asm("{ .reg .u64 t; cvta.to.shared.u64 t, %1; cvt.u32.u64 %0, t; }" : "=r"(a) : "l"(p));
    return a;
}

// bf16x2 mma: D(f32x4) += A(bf16 m16k16) * B(bf16 k16n8)
__device__ __forceinline__ void mma16816(float* d, const uint32_t* a, const uint32_t* b) {
    asm volatile(
        "mma.sync.aligned.m16n8k16.row.col.f32.bf16.bf16.f32 "
        "{%0,%1,%2,%3}, {%4,%5,%6,%7}, {%8,%9}, {%0,%1,%2,%3};"
        : "+f"(d[0]), "+f"(d[1]), "+f"(d[2]), "+f"(d[3])
        : "r"(a[0]), "r"(a[1]), "r"(a[2]), "r"(a[3]), "r"(b[0]), "r"(b[1]));
}

__device__ __forceinline__ void ldsm4(uint32_t* r, uint32_t addr) {
    asm volatile("ldmatrix.sync.aligned.m8n8.x4.shared.b16 {%0,%1,%2,%3}, [%4];"
                 : "=r"(r[0]), "=r"(r[1]), "=r"(r[2]), "=r"(r[3]) : "r"(addr));
}

// fp32 float4 -> (hi bf16x2 pair, lo bf16x2 pair)
__device__ __forceinline__ void split4(float4 v, uint32_t& h0, uint32_t& h1,
                                       uint32_t& l0, uint32_t& l1) {
    asm("cvt.rn.bf16x2.f32 %0, %1, %2;" : "=r"(h0) : "f"(v.y), "f"(v.x));
    asm("cvt.rn.bf16x2.f32 %0, %1, %2;" : "=r"(h1) : "f"(v.w), "f"(v.z));
    float rx = v.x - __uint_as_float(h0 << 16);
    float ry = v.y - __uint_as_float(h0 & 0xFFFF0000u);
    float rz = v.z - __uint_as_float(h1 << 16);
    float rw = v.w - __uint_as_float(h1 & 0xFFFF0000u);
    asm("cvt.rn.bf16x2.f32 %0, %1, %2;" : "=r"(l0) : "f"(ry), "f"(rx));
    asm("cvt.rn.bf16x2.f32 %0, %1, %2;" : "=r"(l1) : "f"(rw), "f"(rz));
}

// ---------------------------------------------------------------------------
// HMMA 3-pass split GEMM. 128x64 tile per CTA (2 CTAs/SM), K chunks of 32,
// 8 warps 4x2 (warp tile 32x32), double-buffered, ldmatrix fragment loads.
#define KST 20              // smem row stride in uint32 (80 B)
#define STGW_A (128*KST)    // 2560 words per A sub-tile
#define STGW_B (64*KST)     // 1280 words per B sub-tile
#define OFF_BHI (2*STGW_A)            // 5120
#define OFF_BLO (2*STGW_A + STGW_B)   // 6400
#define STAGE (2*STGW_A + 2*STGW_B)   // 7680 words = 30720 B

__global__ __launch_bounds__(256, 2) void gemm_cmat_mma(
    const float* __restrict__ tm, const float* __restrict__ dm,
    const float* __restrict__ tb, const float* __restrict__ db,
    const void* __restrict__ act) {
    extern __shared__ uint32_t dyn[];
    __shared__ float s_an[128], s_bn[64], s_dinv[64];
    __shared__ float4 s_tbox[128], s_dbox[64];
    __shared__ float2 s_rmv[2][128];

    int tid = threadIdx.x;
    int b = blockIdx.z, rowBase = blockIdx.y * 128, colBase = blockIdx.x * 64;
    int s4 = probe_s4((const unsigned char*)act);

    int ar = tid >> 1, ah_ = tid & 1;        // A load: row 0..127, k-half
    int br = tid >> 2, bq = tid & 3;         // B load: row 0..63, k-quarter
    const float* aP = tm + ((size_t)(b * Tq + rowBase + ar)) * Dq + ah_ * 16;
    const float* bP = dm + ((size_t)(b * Nq + colBase + br)) * Dq + bq * 8;

    int lane = tid & 31, wid = tid >> 5;
    int wm = wid & 3, wn = wid >> 2;         // warp tile: rows wm*32+, cols wn*32+
    int qrow = lane >> 2, qk = lane & 3;

    // ldmatrix per-lane base addresses (byte offsets within a stage)
    uint32_t sm0 = smem_u32(dyn);
    uint32_t aAddr = sm0 + (uint32_t)(wm * 32 + (lane & 15)) * 80u + (uint32_t)(lane >> 4) * 16u;
    uint32_t bAddr = sm0 + OFF_BHI * 4u
                   + (uint32_t)(wn * 32 + ((lane >> 4) * 8) + (lane & 7)) * 80u
                   + (uint32_t)((lane >> 3) & 1) * 16u;

    float acc[2][4][4];
    #pragma unroll
    for (int mi = 0; mi < 2; mi++)
        #pragma unroll
        for (int ni = 0; ni < 4; ni++)
            #pragma unroll
            for (int q = 0; q < 4; q++) acc[mi][ni][q] = 0.0f;

    float asum = 0.f, bsum = 0.f;
    int kpa = ar * KST + ah_ * 8;
    int kpb = br * KST + bq * 4;

    float4 ra[4], rb[2];
    #pragma unroll
    for (int q = 0; q < 4; q++) ra[q] = *(const float4*)(aP + q * 4);
    rb[0] = *(const float4*)(bP);
    rb[1] = *(const float4*)(bP + 4);

    // prologue: convert+store chunk 0 into stage 0
    {
        uint32_t* st = dyn;
        #pragma unroll
        for (int q = 0; q < 4; q++) {
            float4 v = ra[q];
            asum += v.x*v.x + v.y*v.y + v.z*v.z + v.w*v.w;
            uint32_t h0,h1,l0,l1; split4(v, h0,h1,l0,l1);
            st[kpa + q*2] = h0;            st[kpa + q*2 + 1] = h1;
            st[STGW_A + kpa + q*2] = l0;   st[STGW_A + kpa + q*2 + 1] = l1;
        }
        #pragma unroll
        for (int q = 0; q < 2; q++) {
            float4 v = rb[q];
            bsum += v.x*v.x + v.y*v.y + v.z*v.z + v.w*v.w;
            uint32_t h0,h1,l0,l1; split4(v, h0,h1,l0,l1);
            st[OFF_BHI + kpb + q*2] = h0;  st[OFF_BHI + kpb + q*2 + 1] = h1;
            st[OFF_BLO + kpb + q*2] = l0;  st[OFF_BLO + kpb + q*2 + 1] = l1;
        }
    }
    __syncthreads();

    for (int c = 0; c < 32; c++) {
        if (c < 31) {
            int k0 = (c + 1) * 32;
            #pragma unroll
            for (int q = 0; q < 4; q++) ra[q] = *(const float4*)(aP + k0 + q * 4);
            rb[0] = *(const float4*)(bP + k0);
            rb[1] = *(const float4*)(bP + k0 + 4);
        }
        // MMA on stage c&1
        {
            uint32_t stg = (uint32_t)(c & 1) * (STAGE * 4u);
            #pragma unroll
            for (int s = 0; s < 2; s++) {
                uint32_t ko = stg + (uint32_t)s * 32u;
                uint32_t ahf[2][4], alf[2][4], bhf[4][2], blf[4][2];
                #pragma unroll
                for (int mi = 0; mi < 2; mi++) {
                    ldsm4(ahf[mi], aAddr + ko + (uint32_t)(mi * 16) * 80u);
                    ldsm4(alf[mi], aAddr + ko + (uint32_t)(mi * 16) * 80u + STGW_A * 4u);
                }
                #pragma unroll
                for (int pr = 0; pr < 2; pr++) {
                    uint32_t t4[4];
                    ldsm4(t4, bAddr + ko + (uint32_t)(pr * 16) * 80u);
                    bhf[2*pr][0] = t4[0]; bhf[2*pr][1] = t4[1];
                    bhf[2*pr+1][0] = t4[2]; bhf[2*pr+1][1] = t4[3];
                    ldsm4(t4, bAddr + ko + (uint32_t)(pr * 16) * 80u + STGW_B * 4u);
                    blf[2*pr][0] = t4[0]; blf[2*pr][1] = t4[1];
                    blf[2*pr+1][0] = t4[2]; blf[2*pr+1][1] = t4[3];
                }
                // pass-major order: dependent MMAs on one acc are 8 apart
                #pragma unroll
                for (int mi = 0; mi < 2; mi++)
                    #pragma unroll
                    for (int ni = 0; ni < 4; ni++) mma16816(acc[mi][ni], ahf[mi], bhf[ni]);
                #pragma unroll
                for (int mi = 0; mi < 2; mi++)
                    #pragma unroll
                    for (int ni = 0; ni < 4; ni++) mma16816(acc[mi][ni], ahf[mi], blf[ni]);
                #pragma unroll
                for (int mi = 0; mi < 2; mi++)
                    #pragma unroll
                    for (int ni = 0; ni < 4; ni++) mma16816(acc[mi][ni], alf[mi], bhf[ni]);
            }
        }
        // convert+store chunk c+1 into the other stage
        if (c < 31) {
            uint32_t* st = dyn + ((c + 1) & 1) * STAGE;
            #pragma unroll
            for (int q = 0; q < 4; q++) {
                float4 v = ra[q];
                asum += v.x*v.x + v.y*v.y + v.z*v.z + v.w*v.w;
                uint32_t h0,h1,l0,l1; split4(v, h0,h1,l0,l1);
                st[kpa + q*2] = h0;            st[kpa + q*2 + 1] = h1;
                st[STGW_A + kpa + q*2] = l0;   st[STGW_A + kpa + q*2 + 1] = l1;
            }
            #pragma unroll
            for (int q = 0; q < 2; q++) {
                float4 v = rb[q];
                bsum += v.x*v.x + v.y*v.y + v.z*v.z + v.w*v.w;
                uint32_t h0,h1,l0,l1; split4(v, h0,h1,l0,l1);
                st[OFF_BHI + kpb + q*2] = h0;  st[OFF_BHI + kpb + q*2 + 1] = h1;
                st[OFF_BLO + kpb + q*2] = l0;  st[OFF_BLO + kpb + q*2 + 1] = l1;
            }
        }
        __syncthreads();
    }

    // norms
    asum += __shfl_xor_sync(0xffffffffu, asum, 1);              // A: partner k-half
    bsum += __shfl_xor_sync(0xffffffffu, bsum, 1);              // B: 4 lanes/row
    bsum += __shfl_xor_sync(0xffffffffu, bsum, 2);
    if ((tid & 1) == 0) s_an[ar] = asum;
    if ((tid & 3) == 0) s_bn[br] = bsum;
    if (tid < 128) s_tbox[tid] = ((const float4*)tb)[b * Tq + rowBase + tid];
    if (tid >= 128 && tid < 192) s_dbox[tid - 128] = ((const float4*)db)[b * Nq + colBase + tid - 128];
    __syncthreads();
    if (tid < 64) s_dinv[tid] = 1.0f / fmaxf(sqrtf(s_bn[tid]), 1e-12f);
    __syncthreads();

    #pragma unroll
    for (int mi = 0; mi < 2; mi++) {
        #pragma unroll
        for (int half = 0; half < 2; half++) {
            int lr = wm * 32 + mi * 16 + half * 8 + qrow;
            int gt = rowBase + lr;
            float ti = 1.0f / fmaxf(sqrtf(s_an[lr]), 1e-12f);
            float4 tbx = s_tbox[lr];
            bool aa = get_active(act, b * Tq + gt, s4);
            float tx1 = tbx.x - 0.5f * tbx.z, tx2 = tbx.x + 0.5f * tbx.z;
            float ty1 = tbx.y - 0.5f * tbx.w, ty2 = tbx.y + 0.5f * tbx.w;
            float tarea = tbx.z * tbx.w;
            float best = -2.0f; int barg = 0;
            float* dst = g_C + ((size_t)(b * Tq + gt)) * Nq + colBase;
            #pragma unroll
            for (int ni = 0; ni < 4; ni++) {
                int lc = wn * 32 + ni * 8 + qk * 2;
                float2 o;
                #pragma unroll
                for (int j = 0; j < 2; j++) {
                    float dot = acc[mi][ni][half * 2 + j];
                    float4 dv = s_dbox[lc + j];
                    float dx1 = dv.x - 0.5f * dv.z, dx2 = dv.x + 0.5f * dv.z;
                    float dy1 = dv.y - 0.5f * dv.w, dy2 = dv.y + 0.5f * dv.w;
                    float iw = fmaxf(fminf(tx2, dx2) - fmaxf(tx1, dx1), 0.0f);
                    float ih = fmaxf(fminf(ty2, dy2) - fmaxf(ty1, dy1), 0.0f);
                    float inter = iw * ih;
                    float uni = tarea + dv.z * dv.w - inter;
                    float iou = inter / (uni + 1e-6f);
                    float cv = 0.7f * (dot * ti * s_dinv[lc + j]) + 0.3f * iou;
                    cv = aa ? cv : -1.0f;
                    if (cv > best) { best = cv; barg = lc + j; }
                    (&o.x)[j] = cv;
                }
                *(float2*)(dst + lc) = o;
            }
            #pragma unroll
            for (int off = 1; off <= 2; off <<= 1) {
                float ov = __shfl_xor_sync(0xffffffffu, best, off);
                int   oa = __shfl_xor_sync(0xffffffffu, barg, off);
                if (ov > best || (ov == best && oa < barg)) { best = ov; barg = oa; }
            }
            if (qk == 0) s_rmv[wn][lr] = make_float2(best, __int_as_float(colBase + barg));
        }
    }
    __syncthreads();
    if (tid < 128) {
        float2 m0 = s_rmv[0][tid], m1 = s_rmv[1][tid];
        float2 mm = (m1.x > m0.x) ? m1 : m0;
        g_rmax[(b * Tq + rowBase + tid) * 4 + blockIdx.x] = mm;
    }
}

// ---------------------------------------------------------------------------
// Greedy matching, one warp per batch. Fast path reads g_rmax only.
__global__ __launch_bounds__(32) void greedy_kernel() {
    int b = blockIdx.x;
    int l = threadIdx.x;

    float rmax[8]; int rarg[8];
    #pragma unroll
    for (int i = 0; i < 8; i++) {
        int row = i * 32 + l;
        float v = -3.0f; int a = 0;
        #pragma unroll
        for (int t = 0; t < 4; t++) {
            float2 m = g_rmax[(b * Tq + row) * 4 + t];
            if (m.x > v) { v = m.x; a = __float_as_int(m.y); }
        }
        rmax[i] = v; rarg[i] = a;
    }

    // fast-path distinctness check
    unsigned cm[8] = {0,0,0,0,0,0,0,0};
    int cnt = 0;
    #pragma unroll
    for (int i = 0; i < 8; i++)
        if (rmax[i] >= 0.7f) { cnt++; cm[rarg[i] >> 5] |= 1u << (rarg[i] & 31); }
    int lpop = 0;
    #pragma unroll
    for (int w = 0; w < 8; w++) lpop += __popc(cm[w]);
    int totc = __reduce_add_sync(0xffffffffu, cnt);
    int orp = 0;
    #pragma unroll
    for (int w = 0; w < 8; w++) orp += __popc(__reduce_or_sync(0xffffffffu, cm[w]));
    bool dup = (lpop != cnt);
    bool conflict = __any_sync(0xffffffffu, dup) || (orp != totc);

    if (!conflict) {
        #pragma unroll
        for (int i = 0; i < 8; i++)
            g_match[b * Tq + i * 32 + l] = (rmax[i] >= 0.7f) ? rarg[i] : -1;
        return;
    }

    // slow path: exact sequential greedy (value desc, flat-index asc tiebreak)
    #pragma unroll
    for (int i = 0; i < 8; i++) g_match[b * Tq + i * 32 + l] = -1;
    unsigned taken[8] = {0,0,0,0,0,0,0,0};
    for (int it = 0; it < 256; it++) {
        float bv = rmax[0]; int bi = 0;
        #pragma unroll
        for (int i = 1; i < 8; i++) if (rmax[i] > bv) { bv = rmax[i]; bi = i; }
        int brow = bi * 32 + l;
        #pragma unroll
        for (int off = 16; off; off >>= 1) {
            float ov = __shfl_xor_sync(0xffffffffu, bv, off);
            int orow  = __shfl_xor_sync(0xffffffffu, brow, off);
            if (ov > bv || (ov == bv && orow < brow)) { bv = ov; brow = orow; }
        }
        if (bv < 0.7f) break;
        int ol = brow & 31, oi = brow >> 5;
        int d = __shfl_sync(0xffffffffu, rarg[oi], ol);
        taken[d >> 5] |= 1u << (d & 31);
        if (l == ol) { g_match[b * Tq + brow] = d; rmax[oi] = -3.0f; }
        #pragma unroll
        for (int i = 0; i < 8; i++) {
            if (rmax[i] >= 0.7f && rarg[i] == d) {
                int row = i * 32 + l;
                const float* rr = g_C + ((size_t)b * Tq + row) * Nq;
                float best = -2.0f; int arg = 0;
                for (int n = 0; n < 256; n++) {
                    if (taken[n >> 5] & (1u << (n & 31))) continue;
                    float c = rr[n];
                    if (c > best) { best = c; arg = n; }
                }
                rmax[i] = best; rarg[i] = arg;
            }
        }
    }
}

// ---------------------------------------------------------------------------
// Output assembly + scores (fused).
#define NR (Bq*Tq/4)

__global__ __launch_bounds__(256) void output_kernel(
    const float* __restrict__ tm, const float* __restrict__ dm,
    const float* __restrict__ tb, const float* __restrict__ db,
    const void* __restrict__ act, const int* __restrict__ age,
    const int* __restrict__ hits, const float* __restrict__ logits,
    float* __restrict__ out) {
    int blk = blockIdx.x;
    if (blk < NR) {
        int row = blk * 4 + (threadIdx.x >> 6);
        int b = row >> 8;
        int m = g_match[row];
        const float* src = (m >= 0) ? (dm + ((size_t)b * Nq + m) * Dq)
                                    : (tm + (size_t)row * Dq);
        int j = threadIdx.x & 63;
        float4 v0 = ((const float4*)src)[j];
        float4 v1 = ((const float4*)src)[j + 64];
        float4 v2 = ((const float4*)src)[j + 128];
        float4 v3 = ((const float4*)src)[j + 192];
        float4* dst = (float4*)(out + (size_t)row * Dq);
        dst[j] = v0; dst[j + 64] = v1; dst[j + 128] = v2; dst[j + 192] = v3;
    } else if (blk < NR + Bq) {
        int s4 = probe_s4((const unsigned char*)act);
        int b = blk - NR;
        int t = threadIdx.x;
        int idx = b * Tq + t;
        int m = g_match[idx];
        bool matched = m >= 0;
        int d = matched ? m : 0;
        bool a = get_active(act, idx, s4);
        int h = hits[idx] + (matched ? 1 : 0);
        bool unm = a && !matched;
        int ag = age[idx];
        int newage = matched ? 0 : (unm ? ag + 1 : ag);
        bool newact = matched ? true : (unm ? (newage <= 10) : a);
        float4 bx = matched ? ((const float4*)db)[b * Nq + d]
                            : ((const float4*)tb)[idx];
        ((float4*)(out + OFF_BOX))[idx] = bx;
        out[OFF_ACT   + idx] = newact ? 1.0f : 0.0f;
        out[OFF_AGE   + idx] = (float)newage;
        out[OFF_HITS  + idx] = (float)h;
        out[OFF_MATCH + idx] = (float)m;
    } else {
        int row = (blk - NR - Bq) * 8 + (threadIdx.x >> 5);
        int lane = threadIdx.x & 31;
        const float* p = logits + (size_t)row * Cq;
        float a = p[lane];
        float bb = p[lane + 32];
        bool hasc = (lane + 64) < Cq;
        float c = hasc ? p[lane + 64] : -INFINITY;
        float m = fmaxf(a, fmaxf(bb, c));
        #pragma unroll
        for (int off = 16; off; off >>= 1) m = fmaxf(m, __shfl_xor_sync(0xffffffffu, m, off));
        float s = expf(a - m) + expf(bb - m) + (hasc ? expf(c - m) : 0.0f);
        #pragma unroll
        for (int off = 16; off; off >>= 1) s += __shfl_xor_sync(0xffffffffu, s, off);
        if (lane == 0) out[OFF_SCORES + row] = 1.0f / s;
    }
}

// ---------------------------------------------------------------------------
extern "C" void kernel_launch(void* const* d_in, const int* in_sizes, int n_in,
                              void* d_out, int out_size) {
    const float* tm   = (const float*)d_in[0];
    const float* tb   = (const float*)d_in[1];
    const void*  act  = d_in[2];
    const int*   age  = (const int*)d_in[3];
    const int*   hits = (const int*)d_in[4];
    const float* db   = (const float*)d_in[5];
    const float* dm   = (const float*)d_in[6];
    const float* cl   = (const float*)d_in[7];
    float* out = (float*)d_out;

    static int cfg_done = 0;
    int smem_bytes = 2 * STAGE * 4;   // 61440
    if (!cfg_done) {
        cudaFuncSetAttribute(gemm_cmat_mma,
                             cudaFuncAttributeMaxDynamicSharedMemorySize, smem_bytes);
        cfg_done = 1;
    }

    dim3 g(Nq/64, Tq/128, Bq);
    gemm_cmat_mma<<<g, 256, smem_bytes>>>(tm, dm, tb, db, act);
    greedy_kernel<<<Bq, 32>>>();
    output_kernel<<<NR + Bq + (Bq*Nq)/8, 256>>>(tm, dm, tb, db, act, age, hits, cl, out);
}